// round 9
// baseline (speedup 1.0000x reference)
#include <cuda_runtime.h>
#include <cuda_bf16.h>
#include <math.h>
#include <stdint.h>

#define TN 16384
#define HH 200
#define PL 16
#define NP 3200
#define UD 400
#define K3U 1216     // [0,400) AhBh | [400,800) AlBh | [800,1200) AhBl | pad 16
#define K3M 640      // [0,200) AhBh | [200,400) AlBh | [400,600) AhBl | pad 40
#define BM 256
#define BN 128
#define BK 64
#define NSTG 3

// ---------------- static device scratch ----------------
__device__ float g_Ps[(size_t)TN * NP];
__device__ float g_Pe[(size_t)TN * NP];
__device__ __nv_bfloat16 g_U3[(size_t)TN * K3U];     // [Uhi | Ulo | Uhi | 0]
__device__ __nv_bfloat16 g_B23[2][(size_t)NP * K3U]; // [Whi | Whi | Wlo | 0], n permuted
__device__ __nv_bfloat16 g_B33[2][(size_t)NP * K3M]; // [Whi | Whi | Wlo | 0], n permuted
__device__ __nv_bfloat16 g_m13[2][(size_t)TN * K3M]; // [m1hi | m1lo | m1hi | 0]
__device__ float g_b3p[2][NP];
__device__ float g_m1f[2][(size_t)TN * HH];
__device__ float g_m2f[2][(size_t)TN * HH];
__device__ float g_h[HH], g_c[HH], g_hc[HH];
__device__ float g_gates[4 * HH];
__device__ float g_r[2][HH];
__device__ float g_q[2][NP];
__device__ int g_start, g_end, g_done;

// ---------------- ptx helpers ----------------
__device__ __forceinline__ uint32_t smem_u32(const void* p) {
    uint32_t a;
    asm("{ .reg .u64 t; cvta.to.shared.u64 t, %1; cvt.u32.u64 %0, t; }" : "=r"(a) : "l"(p));
    return a;
}
__device__ __forceinline__ void ldm_x4(uint32_t* r, uint32_t a) {
    asm volatile("ldmatrix.sync.aligned.m8n8.x4.shared.b16 {%0,%1,%2,%3}, [%4];"
                 : "=r"(r[0]), "=r"(r[1]), "=r"(r[2]), "=r"(r[3]) : "r"(a));
}
__device__ __forceinline__ void mma16816(float* c, const uint32_t* a, const uint32_t* b) {
    asm volatile(
        "mma.sync.aligned.m16n8k16.row.col.f32.bf16.bf16.f32 "
        "{%0,%1,%2,%3}, {%4,%5,%6,%7}, {%8,%9}, {%0,%1,%2,%3};"
        : "+f"(c[0]), "+f"(c[1]), "+f"(c[2]), "+f"(c[3])
        : "r"(a[0]), "r"(a[1]), "r"(a[2]), "r"(a[3]), "r"(b[0]), "r"(b[1]));
}
__device__ __forceinline__ void cp16(uint32_t dst, const void* src) {
    asm volatile("cp.async.cg.shared.global [%0], [%1], 16;" :: "r"(dst), "l"(src));
}
__device__ __forceinline__ void cp_commit() {
    asm volatile("cp.async.commit_group;" ::: "memory");
}
__device__ __forceinline__ void cp_wait1() {
    asm volatile("cp.async.wait_group 1;" ::: "memory");
}

// ---------------- conversion kernels ----------------
__global__ void k_convU3(const float* __restrict__ U) {
    size_t idx = (size_t)blockIdx.x * blockDim.x + threadIdx.x;
    if (idx >= (size_t)TN * K3U) return;
    int k = (int)(idx % K3U);
    size_t t = idx / K3U;
    int seg = k / 400, kk = k - seg * 400;
    __nv_bfloat16 o = __float2bfloat16(0.f);
    if (seg < 3) {
        float v = U[t * UD + kk];
        __nv_bfloat16 hi = __float2bfloat16(v);
        o = (seg == 1) ? __float2bfloat16(v - __bfloat162float(hi)) : hi;
    }
    g_U3[idx] = o;
}
// fc2 weight (first 400 cols), n permuted: n = j*16+p <- src row p*200+j
__global__ void k_convB23(const float* __restrict__ w2, int head) {
    size_t idx = (size_t)blockIdx.x * blockDim.x + threadIdx.x;
    if (idx >= (size_t)NP * K3U) return;
    int k = (int)(idx % K3U);
    int n = (int)(idx / K3U);
    int j = n >> 4, p = n & 15;
    int seg = k / 400, kk = k - seg * 400;
    __nv_bfloat16 o = __float2bfloat16(0.f);
    if (seg < 3) {
        float v = w2[(size_t)(p * 200 + j) * 600 + kk];
        __nv_bfloat16 hi = __float2bfloat16(v);
        o = (seg == 2) ? __float2bfloat16(v - __bfloat162float(hi)) : hi;
    }
    g_B23[head][idx] = o;
}
// fc3 weight, n permuted. segs of 200 at 0/200/400, tail [600,640) zero.
__global__ void k_convB33(const float* __restrict__ w3, const float* __restrict__ b3, int head) {
    size_t idx = (size_t)blockIdx.x * blockDim.x + threadIdx.x;
    if (idx >= (size_t)NP * K3M) return;
    int k = (int)(idx % K3M);
    int n = (int)(idx / K3M);
    int j = n >> 4, p = n & 15;
    int src = p * 200 + j;
    int seg = k / 200;               // 3 for tail
    int kk = k - seg * 200;
    __nv_bfloat16 o = __float2bfloat16(0.f);
    if (seg < 3) {
        float v = w3[(size_t)src * HH + kk];
        __nv_bfloat16 hi = __float2bfloat16(v);
        o = (seg == 2) ? __float2bfloat16(v - __bfloat162float(hi)) : hi;
    }
    g_B33[head][idx] = o;
    if (k == 0) g_b3p[head][n] = b3[src];
}
__global__ void k_zero13() {   // zero m13 tails [600,640) once, both heads
    int idx = blockIdx.x * blockDim.x + threadIdx.x;
    int h = idx & 1;
    int r = idx >> 1;
    int t = r / 40, k = r - (r / 40) * 40;
    if (t < TN) g_m13[h][(size_t)t * K3M + 600 + k] = __float2bfloat16(0.f);
}
__global__ void k_init() {
    int j = threadIdx.x;
    if (j < HH) { g_h[j] = 0.f; g_c[j] = 0.f; }
    if (j == 0) { g_start = 0; g_end = 0; g_done = 0; }
}

// ---------------- HMMA GEMM (cp.async 3-stage, 64x64 warp tile) ----------------
// mode 0: C[TN,NP] = U3 @ B23[head]^T -> fp32 g_Ps/g_Pe     (NC=19)
// mode 1: fused fc3: maxpool16(m13 @ B33[head]^T + bias) -> g_m2f[head]  (NC=10)
// head = blockIdx.z. BM=256 BN=128 BK=64, 256 thr, 8 warps (4m x 2n), warp 64x64.
#define SMEM_STAGE 49152      // A 32KB + B 16KB
#define SMEM_BYTES (NSTG * SMEM_STAGE)

__global__ void __launch_bounds__(256) k_mma(int mode) {
    if (mode == 1 && g_done) return;
    extern __shared__ char smem[];
    __shared__ float s_bias[BN];
    const uint32_t sb = smem_u32(smem);
    const int tid = threadIdx.x;
    const int head = blockIdx.z;
    const int wid = tid >> 5, lane = tid & 31;
    const int wm = wid >> 1, wn = wid & 1;          // 4m x 2n warps
    const int bm = blockIdx.y * BM, bn = blockIdx.x * BN;
    const int K3 = mode ? K3M : K3U;
    const int NC = K3 / BK;
    const __nv_bfloat16* A = mode ? g_m13[head] : g_U3;
    const __nv_bfloat16* B = mode ? g_B33[head] : g_B23[head];

    if (mode == 1 && tid < BN) s_bias[tid] = g_b3p[head][bn + tid];

    // A loader: thread tid owns row tid (8 x 16B chunks)
    const __nv_bfloat16* gA = A + (size_t)(bm + tid) * K3;
    // B loader: thread owns row tid>>1, 64B half (tid&1) (4 x 16B chunks)
    const int brow = tid >> 1, bseg = tid & 1;
    const __nv_bfloat16* gB = B + (size_t)(bn + brow) * K3 + bseg * 32;

    uint32_t aoff[8], boff[4];
#pragma unroll
    for (int i = 0; i < 8; i++) {
        uint32_t off = (uint32_t)tid * 128 + i * 16;
        aoff[i] = off ^ ((off >> 3) & 0x70);
    }
#pragma unroll
    for (int i = 0; i < 4; i++) {
        uint32_t off = (uint32_t)brow * 128 + bseg * 64 + i * 16;
        boff[i] = off ^ ((off >> 3) & 0x70);
    }

#define ISSUE(c)                                                       \
    {                                                                  \
        const uint32_t st = sb + ((c) % NSTG) * SMEM_STAGE;            \
        const int k0 = (c) * BK;                                       \
        _Pragma("unroll")                                              \
        for (int i = 0; i < 8; i++) cp16(st + aoff[i], gA + k0 + i * 8); \
        _Pragma("unroll")                                              \
        for (int i = 0; i < 4; i++) cp16(st + 32768 + boff[i], gB + k0 + i * 8); \
    }

    float acc[4][8][4];
#pragma unroll
    for (int i = 0; i < 4; i++)
#pragma unroll
        for (int j = 0; j < 8; j++)
#pragma unroll
            for (int q = 0; q < 4; q++) acc[i][j][q] = 0.f;

    ISSUE(0); cp_commit();
    ISSUE(1); cp_commit();

    for (int c = 0; c < NC; c++) {
        cp_wait1();
        __syncthreads();
        if (c + 2 < NC) ISSUE(c + 2);
        cp_commit();                         // empty group in tail keeps counting aligned

        const uint32_t base = sb + (c % NSTG) * SMEM_STAGE;
#pragma unroll
        for (int kk = 0; kk < 4; kk++) {
            uint32_t af[4][4];
#pragma unroll
            for (int i = 0; i < 4; i++) {
                uint32_t off = (uint32_t)(wm * 64 + i * 16 + (lane & 15)) * 128
                             + kk * 32 + ((lane >> 4) & 1) * 16;
                uint32_t sw = off ^ ((off >> 3) & 0x70);
                ldm_x4(af[i], base + sw);
            }
            uint32_t bf[4][4];
#pragma unroll
            for (int j = 0; j < 4; j++) {
                uint32_t nrow = wn * 64 + j * 16 + (lane & 7) + ((lane >> 4) & 1) * 8;
                uint32_t off = nrow * 128 + kk * 32 + ((lane >> 3) & 1) * 16;
                uint32_t sw = off ^ ((off >> 3) & 0x70);
                ldm_x4(bf[j], base + 32768 + sw);
            }
#pragma unroll
            for (int i = 0; i < 4; i++)
#pragma unroll
                for (int j = 0; j < 4; j++) {
                    mma16816(acc[i][2 * j], af[i], &bf[j][0]);
                    mma16816(acc[i][2 * j + 1], af[i], &bf[j][2]);
                }
        }
    }
#undef ISSUE

    // ---------------- epilogue ----------------
    if (mode == 0) {
        float* C = head ? g_Pe : g_Ps;
        const int r0 = bm + wm * 64, n0 = bn + wn * 64;
#pragma unroll
        for (int i = 0; i < 4; i++)
#pragma unroll
            for (int jt = 0; jt < 8; jt++) {
                int row = r0 + i * 16 + (lane >> 2);
                int col = n0 + jt * 8 + (lane & 3) * 2;
                *(float2*)(C + (size_t)row * NP + col) =
                    make_float2(acc[i][jt][0], acc[i][jt][1]);
                *(float2*)(C + (size_t)(row + 8) * NP + col) =
                    make_float2(acc[i][jt][2], acc[i][jt][3]);
            }
    } else {
        const int r0 = bm + wm * 64;
        const int j0 = (bn >> 4) + wn * 4;
        float* m2 = g_m2f[head];
#pragma unroll
        for (int i = 0; i < 4; i++)
#pragma unroll
            for (int g = 0; g < 4; g++) {
                int nb = wn * 64 + g * 16 + (lane & 3) * 2;
                float b0 = s_bias[nb], b1 = s_bias[nb + 1];
                float b2 = s_bias[nb + 8], b3 = s_bias[nb + 9];
                float v0 = fmaxf(fmaxf(acc[i][2 * g][0] + b0, acc[i][2 * g][1] + b1),
                                 fmaxf(acc[i][2 * g + 1][0] + b2, acc[i][2 * g + 1][1] + b3));
                float v1 = fmaxf(fmaxf(acc[i][2 * g][2] + b0, acc[i][2 * g][3] + b1),
                                 fmaxf(acc[i][2 * g + 1][2] + b2, acc[i][2 * g + 1][3] + b3));
                v0 = fmaxf(v0, __shfl_xor_sync(0xffffffffu, v0, 1));
                v0 = fmaxf(v0, __shfl_xor_sync(0xffffffffu, v0, 2));
                v1 = fmaxf(v1, __shfl_xor_sync(0xffffffffu, v1, 1));
                v1 = fmaxf(v1, __shfl_xor_sync(0xffffffffu, v1, 2));
                if ((lane & 3) == 0) {
                    int row = r0 + i * 16 + (lane >> 2);
                    m2[(size_t)row * HH + j0 + g] = v0;
                    m2[(size_t)(row + 8) * HH + j0 + g] = v1;
                }
            }
    }
}

// ---------------- m1 pool: P + q -> max16 -> m1f (fp32) + m13 (triple bf16) ----
// blockIdx.y = head
__global__ void k_pool1() {
    if (g_done) return;
    int head = blockIdx.y;
    int idx = blockIdx.x * blockDim.x + threadIdx.x;
    int t = idx / HH;
    int j = idx - t * HH;
    if (t >= TN) return;
    const float* P = (head ? g_Pe : g_Ps) + (size_t)t * NP + j * 16;
    const float* q = g_q[head] + j * 16;
    float m = P[0] + q[0];
#pragma unroll
    for (int p = 1; p < PL; p++) m = fmaxf(m, P[p] + q[p]);
    g_m1f[head][(size_t)t * HH + j] = m;
    __nv_bfloat16 hi = __float2bfloat16(m);
    __nv_bfloat16 lo = __float2bfloat16(m - __bfloat162float(hi));
    __nv_bfloat16* row = g_m13[head] + (size_t)t * K3M;
    row[j] = hi;                 // seg0: hi
    row[200 + j] = lo;           // seg1: lo
    row[400 + j] = hi;           // seg2: hi
}

// ---------------- small per-iteration kernels ----------------
__global__ void k_gates(const float* __restrict__ U, const float* __restrict__ Wih,
                        const float* __restrict__ Whh, const float* __restrict__ bih,
                        const float* __restrict__ bhh)
{
    if (g_done) return;
    int w = (blockIdx.x * blockDim.x + threadIdx.x) >> 5;
    int lane = threadIdx.x & 31;
    if (w >= 4 * HH) return;
    const float* Us = U + (size_t)g_start * UD;
    const float* Ue = U + (size_t)g_end * UD;
    const float* wr = Wih + (size_t)w * 800;
    const float* hr = Whh + (size_t)w * HH;
    float s = 0.f;
    for (int k = lane; k < UD; k += 32) s = fmaf(Us[k], wr[k], s);
    for (int k = lane; k < UD; k += 32) s = fmaf(Ue[k], wr[400 + k], s);
    for (int k = lane; k < HH; k += 32) s = fmaf(g_h[k], hr[k], s);
    for (int off = 16; off; off >>= 1) s += __shfl_xor_sync(0xffffffffu, s, off);
    if (lane == 0) g_gates[w] = s + bih[w] + bhh[w];
}

__device__ __forceinline__ float sigm(float x) { return 1.f / (1.f + expf(-x)); }

__global__ void k_lstm_update() {
    if (g_done) return;
    int j = threadIdx.x;
    if (j < HH) {
        float i = sigm(g_gates[j]);
        float f = sigm(g_gates[HH + j]);
        float g = tanhf(g_gates[2 * HH + j]);
        float o = sigm(g_gates[3 * HH + j]);
        float cc = f * g_c[j] + i * g;
        float hc = o * tanhf(cc);
        g_hc[j] = hc;
        g_h[j] = hc;
        g_c[j] = cc;
    }
}

__global__ void k_r(const float* __restrict__ U,
                    const float* __restrict__ w1s, const float* __restrict__ w1e)
{
    if (g_done) return;
    int w = (blockIdx.x * blockDim.x + threadIdx.x) >> 5;
    int lane = threadIdx.x & 31;
    if (w >= 2 * HH) return;
    int head = w / HH;
    int j = w - head * HH;
    const float* row = (head ? w1e : w1s) + (size_t)j * 1000;
    const float* Us = U + (size_t)g_start * UD;
    const float* Ue = U + (size_t)g_end * UD;
    float s = 0.f;
    for (int k = lane; k < HH; k += 32) s = fmaf(g_hc[k], row[k], s);
    for (int k = lane; k < UD; k += 32) s = fmaf(Us[k], row[200 + k], s);
    for (int k = lane; k < UD; k += 32) s = fmaf(Ue[k], row[600 + k], s);
    for (int off = 16; off; off >>= 1) s += __shfl_xor_sync(0xffffffffu, s, off);
    if (lane == 0) g_r[head][j] = tanhf(s);
}

// q'[head][j*16+p] = r[head] @ w2[p*200+j, 400:600] + b2[p*200+j]
__global__ void k_q(const float* __restrict__ w2s, const float* __restrict__ b2s,
                    const float* __restrict__ w2e, const float* __restrict__ b2e)
{
    if (g_done) return;
    int w = (blockIdx.x * blockDim.x + threadIdx.x) >> 5;
    int lane = threadIdx.x & 31;
    if (w >= 2 * NP) return;
    int head = w / NP;
    int n = w - head * NP;
    int j = n >> 4, p = n & 15;
    int src = p * 200 + j;
    const float* row = (head ? w2e : w2s) + (size_t)src * 600 + 400;
    const float* b2 = head ? b2e : b2s;
    const float* r = g_r[head];
    float s = 0.f;
    for (int k = lane; k < HH; k += 32) s = fmaf(r[k], row[k], s);
    for (int off = 16; off; off >>= 1) s += __shfl_xor_sync(0xffffffffu, s, off);
    if (lane == 0) g_q[head][n] = s + b2[src];
}

// blockIdx.y = head
__global__ void k_fc4(const float* __restrict__ w4s, const float* __restrict__ b4s,
                      const float* __restrict__ w4e, const float* __restrict__ b4e,
                      float* __restrict__ out, int it)
{
    int head = blockIdx.y;
    const float* w4 = head ? w4e : w4s;
    const float* b4 = head ? b4e : b4s;
    float* outRow = out + (size_t)(head * 4 + it) * TN;
    int t = (blockIdx.x * blockDim.x + threadIdx.x) >> 5;
    int lane = threadIdx.x & 31;
    if (t >= TN) return;
    if (it > 0 && g_done) {
        if (lane == 0) outRow[t] = (outRow - TN)[t];
        return;
    }
    const float* m1r = g_m1f[head] + (size_t)t * HH;
    const float* m2r = g_m2f[head] + (size_t)t * HH;
    float acc[PL];
#pragma unroll
    for (int p = 0; p < PL; p++) acc[p] = 0.f;
    for (int k = lane; k < HH; k += 32) {
        float v1 = m1r[k], v2 = m2r[k];
#pragma unroll
        for (int p = 0; p < PL; p++) {
            acc[p] = fmaf(v1, w4[p * 400 + k], acc[p]);
            acc[p] = fmaf(v2, w4[p * 400 + 200 + k], acc[p]);
        }
    }
#pragma unroll
    for (int p = 0; p < PL; p++)
        for (int off = 16; off; off >>= 1)
            acc[p] += __shfl_xor_sync(0xffffffffu, acc[p], off);
    if (lane == 0) {
        float best = acc[0] + b4[0];
#pragma unroll
        for (int p = 1; p < PL; p++) best = fmaxf(best, acc[p] + b4[p]);
        outRow[t] = best;
    }
}

__global__ void k_update(const float* __restrict__ arow, const float* __restrict__ brow,
                         int it)
{
    if (it > 0 && g_done) return;
    __shared__ float sv[256];
    __shared__ int si[256];
    __shared__ int res[2];
    int tid = threadIdx.x;
    for (int pass = 0; pass < 2; pass++) {
        const float* row = pass ? brow : arow;
        float bv = -3.4e38f; int bi = 0;
        for (int t = tid; t < TN; t += 256) {
            float v = row[t];
            if (v > bv) { bv = v; bi = t; }
        }
        sv[tid] = bv; si[tid] = bi;
        __syncthreads();
        for (int s = 128; s; s >>= 1) {
            if (tid < s) {
                float ov = sv[tid + s]; int oi = si[tid + s];
                if (ov > sv[tid] || (ov == sv[tid] && oi < si[tid])) {
                    sv[tid] = ov; si[tid] = oi;
                }
            }
            __syncthreads();
        }
        if (tid == 0) res[pass] = si[0];
        __syncthreads();
    }
    if (tid == 0) {
        int ns = res[0], ne = res[1];
        if (it == 0) {
            g_start = ns; g_end = ne; g_done = 0;
        } else {
            int nd = (ns == g_start && ne == g_end);
            g_start = ns; g_end = ne;
            g_done = nd;
        }
    }
}

// ---------------------------------------------------------------------------
extern "C" void kernel_launch(void* const* d_in, const int* in_sizes, int n_in,
                              void* d_out, int out_size)
{
    const float* U        = (const float*)d_in[0];
    const float* lstm_Wih = (const float*)d_in[1];
    const float* lstm_Whh = (const float*)d_in[2];
    const float* lstm_bih = (const float*)d_in[3];
    const float* lstm_bhh = (const float*)d_in[4];
    const float* s_fc1w = (const float*)d_in[5];
    const float* s_fc2w = (const float*)d_in[6];
    const float* s_fc2b = (const float*)d_in[7];
    const float* s_fc3w = (const float*)d_in[8];
    const float* s_fc3b = (const float*)d_in[9];
    const float* s_fc4w = (const float*)d_in[10];
    const float* s_fc4b = (const float*)d_in[11];
    const float* e_fc1w = (const float*)d_in[12];
    const float* e_fc2w = (const float*)d_in[13];
    const float* e_fc2b = (const float*)d_in[14];
    const float* e_fc3w = (const float*)d_in[15];
    const float* e_fc3b = (const float*)d_in[16];
    const float* e_fc4w = (const float*)d_in[17];
    const float* e_fc4b = (const float*)d_in[18];
    float* out = (float*)d_out;   // [alphas 4*T | betas 4*T]

    cudaFuncSetAttribute(k_mma, cudaFuncAttributeMaxDynamicSharedMemorySize, SMEM_BYTES);

    dim3 ggrid(NP / BN, TN / BM, 2);   // 25 x 64 x 2 heads

    // launches 0..4, then launch #5 (profiled by ncu -s 5 -c 1) = dual-head precompute
    k_init<<<1, 256>>>();
    k_convU3<<<(TN * K3U + 255) / 256, 256>>>(U);
    k_convB23<<<(NP * K3U + 255) / 256, 256>>>(s_fc2w, 0);
    k_convB23<<<(NP * K3U + 255) / 256, 256>>>(e_fc2w, 1);
    k_zero13<<<(TN * 80 + 255) / 256, 256>>>();
    k_mma<<<ggrid, 256, SMEM_BYTES>>>(0);
    k_convB33<<<(NP * K3M + 255) / 256, 256>>>(s_fc3w, s_fc3b, 0);
    k_convB33<<<(NP * K3M + 255) / 256, 256>>>(e_fc3w, e_fc3b, 1);

    dim3 pgrid((TN * HH + 255) / 256, 2);
    dim3 fgrid((TN * 32) / 256, 2);

    for (int it = 0; it < 4; it++) {
        k_gates<<<100, 256>>>(U, lstm_Wih, lstm_Whh, lstm_bih, lstm_bhh);
        k_lstm_update<<<1, 256>>>();
        k_r<<<50, 256>>>(U, s_fc1w, e_fc1w);
        k_q<<<800, 256>>>(s_fc2w, s_fc2b, e_fc2w, e_fc2b);
        k_pool1<<<pgrid, 256>>>();
        k_mma<<<ggrid, 256, SMEM_BYTES>>>(1);
        k_fc4<<<fgrid, 256>>>(s_fc4w, s_fc4b, e_fc4w, e_fc4b, out, it);
        k_update<<<1, 256>>>(out + (size_t)it * TN, out + (size_t)(4 + it) * TN, it);
    }
}

// round 10
// speedup vs baseline: 1.2918x; 1.2918x over previous
#include <cuda_runtime.h>
#include <cuda_bf16.h>
#include <cuda_fp16.h>
#include <math.h>
#include <stdint.h>

#define TN 16384
#define HH 200
#define PL 16
#define NP 3200
#define UD 400
#define K3U 1216     // bf16 3-term: [0,400) AhBh | [400,800) AlBh | [800,1200) AhBl | pad 16
#define K3M 448      // fp16 2-term: [0,200) m1hi*w3hi | [200,400) m1lo*w3hi | pad 48
#define BM 128
#define BN 128
#define BK 64
#define NSTG 3

// ---------------- static device scratch ----------------
__device__ float g_Ps[(size_t)TN * NP];
__device__ float g_Pe[(size_t)TN * NP];
__device__ __nv_bfloat16 g_U3[(size_t)TN * K3U];       // [Uhi | Ulo | Uhi | 0]
__device__ __nv_bfloat16 g_B23[2][(size_t)NP * K3U];   // [Whi | Whi | Wlo | 0], n permuted
__device__ unsigned short g_B33[2][(size_t)NP * K3M];  // fp16 [w3hi | w3hi | 0], n permuted
__device__ unsigned short g_m13[2][(size_t)TN * K3M];  // fp16 [m1hi | m1lo | 0]
__device__ float g_b3p[2][NP];
__device__ float g_m1f[2][(size_t)TN * HH];
__device__ float g_m2f[2][(size_t)TN * HH];
__device__ float g_h[HH], g_c[HH], g_hc[HH];
__device__ float g_gates[4 * HH];
__device__ float g_r[2][HH];
__device__ float g_q[2][NP];
__device__ int g_start, g_end, g_done;

// ---------------- ptx helpers ----------------
__device__ __forceinline__ uint32_t smem_u32(const void* p) {
    uint32_t a;
    asm("{ .reg .u64 t; cvta.to.shared.u64 t, %1; cvt.u32.u64 %0, t; }" : "=r"(a) : "l"(p));
    return a;
}
__device__ __forceinline__ void ldm_x4(uint32_t* r, uint32_t a) {
    asm volatile("ldmatrix.sync.aligned.m8n8.x4.shared.b16 {%0,%1,%2,%3}, [%4];"
                 : "=r"(r[0]), "=r"(r[1]), "=r"(r[2]), "=r"(r[3]) : "r"(a));
}
__device__ __forceinline__ void mma_bf(float* c, const uint32_t* a, const uint32_t* b) {
    asm volatile(
        "mma.sync.aligned.m16n8k16.row.col.f32.bf16.bf16.f32 "
        "{%0,%1,%2,%3}, {%4,%5,%6,%7}, {%8,%9}, {%0,%1,%2,%3};"
        : "+f"(c[0]), "+f"(c[1]), "+f"(c[2]), "+f"(c[3])
        : "r"(a[0]), "r"(a[1]), "r"(a[2]), "r"(a[3]), "r"(b[0]), "r"(b[1]));
}
__device__ __forceinline__ void mma_fp(float* c, const uint32_t* a, const uint32_t* b) {
    asm volatile(
        "mma.sync.aligned.m16n8k16.row.col.f32.f16.f16.f32 "
        "{%0,%1,%2,%3}, {%4,%5,%6,%7}, {%8,%9}, {%0,%1,%2,%3};"
        : "+f"(c[0]), "+f"(c[1]), "+f"(c[2]), "+f"(c[3])
        : "r"(a[0]), "r"(a[1]), "r"(a[2]), "r"(a[3]), "r"(b[0]), "r"(b[1]));
}
__device__ __forceinline__ void cp16(uint32_t dst, const void* src) {
    asm volatile("cp.async.cg.shared.global [%0], [%1], 16;" :: "r"(dst), "l"(src));
}
__device__ __forceinline__ void cp_commit() {
    asm volatile("cp.async.commit_group;" ::: "memory");
}
__device__ __forceinline__ void cp_wait1() {
    asm volatile("cp.async.wait_group 1;" ::: "memory");
}

// ---------------- conversion kernels ----------------
__global__ void k_convU3(const float* __restrict__ U) {
    size_t idx = (size_t)blockIdx.x * blockDim.x + threadIdx.x;
    if (idx >= (size_t)TN * K3U) return;
    int k = (int)(idx % K3U);
    size_t t = idx / K3U;
    int seg = k / 400, kk = k - seg * 400;
    __nv_bfloat16 o = __float2bfloat16(0.f);
    if (seg < 3) {
        float v = U[t * UD + kk];
        __nv_bfloat16 hi = __float2bfloat16(v);
        o = (seg == 1) ? __float2bfloat16(v - __bfloat162float(hi)) : hi;
    }
    g_U3[idx] = o;
}
// fc2 weight (first 400 cols), n permuted: n = j*16+p <- src row p*200+j
__global__ void k_convB23(const float* __restrict__ w2, int head) {
    size_t idx = (size_t)blockIdx.x * blockDim.x + threadIdx.x;
    if (idx >= (size_t)NP * K3U) return;
    int k = (int)(idx % K3U);
    int n = (int)(idx / K3U);
    int j = n >> 4, p = n & 15;
    int seg = k / 400, kk = k - seg * 400;
    __nv_bfloat16 o = __float2bfloat16(0.f);
    if (seg < 3) {
        float v = w2[(size_t)(p * 200 + j) * 600 + kk];
        __nv_bfloat16 hi = __float2bfloat16(v);
        o = (seg == 2) ? __float2bfloat16(v - __bfloat162float(hi)) : hi;
    }
    g_B23[head][idx] = o;
}
// fc3 weight fp16, n permuted. w3hi at segs 0 and 1, tail [400,448) zero.
__global__ void k_convB33(const float* __restrict__ w3, const float* __restrict__ b3, int head) {
    size_t idx = (size_t)blockIdx.x * blockDim.x + threadIdx.x;
    if (idx >= (size_t)NP * K3M) return;
    int k = (int)(idx % K3M);
    int n = (int)(idx / K3M);
    int j = n >> 4, p = n & 15;
    int src = p * 200 + j;
    int seg = k / 200;               // 0,1 data; 2 = tail
    int kk = k - seg * 200;
    unsigned short o = 0;
    if (seg < 2) {
        float v = w3[(size_t)src * HH + kk];
        o = __half_as_ushort(__float2half_rn(v));
    }
    g_B33[head][idx] = o;
    if (k == 0) g_b3p[head][n] = b3[src];
}
__global__ void k_zero13() {   // zero m13 tails [400,448) once, both heads
    int idx = blockIdx.x * blockDim.x + threadIdx.x;
    int h = idx & 1;
    int r = idx >> 1;
    int t = r / 48, k = r - (r / 48) * 48;
    if (t < TN) g_m13[h][(size_t)t * K3M + 400 + k] = 0;
}
__global__ void k_init() {
    int j = threadIdx.x;
    if (j < HH) { g_h[j] = 0.f; g_c[j] = 0.f; }
    if (j == 0) { g_start = 0; g_end = 0; g_done = 0; }
}

// ---------------- HMMA GEMM (cp.async 3-stage, 32x64 warp tile, head=z) ----------
// mode 0: C[TN,NP] = U3 @ B23[head]^T -> fp32 g_Ps/g_Pe              (bf16, NC=19)
// mode 1: fused fc3: maxpool16(m13 @ B33[head]^T + bias) -> g_m2f[head] (fp16, NC=7)
#define SMEM_STAGE 32768      // A 16KB + B 16KB
#define SMEM_BYTES (NSTG * SMEM_STAGE)

__global__ void __launch_bounds__(256) k_mma(int mode) {
    if (mode == 1 && g_done) return;
    extern __shared__ char smem[];
    __shared__ float s_bias[BN];
    const uint32_t sb = smem_u32(smem);
    const int tid = threadIdx.x;
    const int head = blockIdx.z;
    const int wid = tid >> 5, lane = tid & 31;
    const int wm = wid >> 1, wn = wid & 1;          // warp tile origin (4m x 2n)
    const int bm = blockIdx.y * BM, bn = blockIdx.x * BN;
    const int K3 = mode ? K3M : K3U;
    const int NC = K3 / BK;
    const __nv_bfloat16* A = mode ? (const __nv_bfloat16*)g_m13[head] : g_U3;
    const __nv_bfloat16* B = mode ? (const __nv_bfloat16*)g_B33[head] : g_B23[head];

    if (mode == 1 && tid < BN) s_bias[tid] = g_b3p[head][bn + tid];

    const int lrow = tid >> 1;          // 0..127
    const int lseg = tid & 1;           // 64B half of the 128B row
    const __nv_bfloat16* gA = A + (size_t)(bm + lrow) * K3 + lseg * 32;
    const __nv_bfloat16* gB = B + (size_t)(bn + lrow) * K3 + lseg * 32;

    uint32_t soff[4];
#pragma unroll
    for (int i = 0; i < 4; i++) {
        uint32_t off = (uint32_t)lrow * 128 + lseg * 64 + i * 16;
        soff[i] = off ^ ((off >> 3) & 0x70);
    }

#define ISSUE(c)                                                       \
    {                                                                  \
        const uint32_t st = sb + ((c) % NSTG) * SMEM_STAGE;            \
        const int k0 = (c) * BK;                                       \
        _Pragma("unroll")                                              \
        for (int i = 0; i < 4; i++) {                                  \
            cp16(st + soff[i], gA + k0 + i * 8);                       \
            cp16(st + 16384 + soff[i], gB + k0 + i * 8);               \
        }                                                              \
    }

#define COMPUTE(MMAOP)                                                           \
    {                                                                            \
        _Pragma("unroll")                                                        \
        for (int kk = 0; kk < 4; kk++) {                                         \
            uint32_t af[2][4];                                                   \
            _Pragma("unroll")                                                    \
            for (int i = 0; i < 2; i++) {                                        \
                uint32_t off = (uint32_t)(wm * 32 + i * 16 + (lane & 15)) * 128  \
                             + kk * 32 + ((lane >> 4) & 1) * 16;                 \
                uint32_t sw = off ^ ((off >> 3) & 0x70);                         \
                ldm_x4(af[i], base + sw);                                        \
            }                                                                    \
            uint32_t bf[4][4];                                                   \
            _Pragma("unroll")                                                    \
            for (int j = 0; j < 4; j++) {                                        \
                uint32_t nrow = wn * 64 + j * 16 + (lane & 7) + ((lane >> 4) & 1) * 8; \
                uint32_t off = nrow * 128 + kk * 32 + ((lane >> 3) & 1) * 16;    \
                uint32_t sw = off ^ ((off >> 3) & 0x70);                         \
                ldm_x4(bf[j], base + 16384 + sw);                                \
            }                                                                    \
            _Pragma("unroll")                                                    \
            for (int i = 0; i < 2; i++)                                          \
                _Pragma("unroll")                                                \
                for (int j = 0; j < 4; j++) {                                    \
                    MMAOP(acc[i][2 * j], af[i], &bf[j][0]);                      \
                    MMAOP(acc[i][2 * j + 1], af[i], &bf[j][2]);                  \
                }                                                                \
        }                                                                        \
    }

    float acc[2][8][4];
#pragma unroll
    for (int i = 0; i < 2; i++)
#pragma unroll
        for (int j = 0; j < 8; j++)
#pragma unroll
            for (int q = 0; q < 4; q++) acc[i][j][q] = 0.f;

    ISSUE(0); cp_commit();
    ISSUE(1); cp_commit();

    for (int c = 0; c < NC; c++) {
        cp_wait1();
        __syncthreads();
        if (c + 2 < NC) ISSUE(c + 2);
        cp_commit();                         // empty group in tail keeps counting aligned

        const uint32_t base = sb + (c % NSTG) * SMEM_STAGE;
        if (mode == 0) COMPUTE(mma_bf)
        else           COMPUTE(mma_fp)
    }
#undef ISSUE
#undef COMPUTE

    // ---------------- epilogue ----------------
    if (mode == 0) {
        float* C = head ? g_Pe : g_Ps;
        const int r0 = bm + wm * 32, n0 = bn + wn * 64;
#pragma unroll
        for (int i = 0; i < 2; i++)
#pragma unroll
            for (int jt = 0; jt < 8; jt++) {
                int row = r0 + i * 16 + (lane >> 2);
                int col = n0 + jt * 8 + (lane & 3) * 2;
                *(float2*)(C + (size_t)row * NP + col) =
                    make_float2(acc[i][jt][0], acc[i][jt][1]);
                *(float2*)(C + (size_t)(row + 8) * NP + col) =
                    make_float2(acc[i][jt][2], acc[i][jt][3]);
            }
    } else {
        const int r0 = bm + wm * 32;
        const int j0 = (bn >> 4) + wn * 4;
        float* m2 = g_m2f[head];
#pragma unroll
        for (int i = 0; i < 2; i++)
#pragma unroll
            for (int g = 0; g < 4; g++) {
                int nb = wn * 64 + g * 16 + (lane & 3) * 2;
                float b0 = s_bias[nb], b1 = s_bias[nb + 1];
                float b2 = s_bias[nb + 8], b3 = s_bias[nb + 9];
                float v0 = fmaxf(fmaxf(acc[i][2 * g][0] + b0, acc[i][2 * g][1] + b1),
                                 fmaxf(acc[i][2 * g + 1][0] + b2, acc[i][2 * g + 1][1] + b3));
                float v1 = fmaxf(fmaxf(acc[i][2 * g][2] + b0, acc[i][2 * g][3] + b1),
                                 fmaxf(acc[i][2 * g + 1][2] + b2, acc[i][2 * g + 1][3] + b3));
                v0 = fmaxf(v0, __shfl_xor_sync(0xffffffffu, v0, 1));
                v0 = fmaxf(v0, __shfl_xor_sync(0xffffffffu, v0, 2));
                v1 = fmaxf(v1, __shfl_xor_sync(0xffffffffu, v1, 1));
                v1 = fmaxf(v1, __shfl_xor_sync(0xffffffffu, v1, 2));
                if ((lane & 3) == 0) {
                    int row = r0 + i * 16 + (lane >> 2);
                    m2[(size_t)row * HH + j0 + g] = v0;
                    m2[(size_t)(row + 8) * HH + j0 + g] = v1;
                }
            }
    }
}

// ---------------- m1 pool: P + q -> max16 -> m1f (fp32) + m13 (fp16 hi/lo) ----
// blockIdx.y = head
__global__ void k_pool1() {
    if (g_done) return;
    int head = blockIdx.y;
    int idx = blockIdx.x * blockDim.x + threadIdx.x;
    int t = idx / HH;
    int j = idx - t * HH;
    if (t >= TN) return;
    const float* P = (head ? g_Pe : g_Ps) + (size_t)t * NP + j * 16;
    const float* q = g_q[head] + j * 16;
    float m = P[0] + q[0];
#pragma unroll
    for (int p = 1; p < PL; p++) m = fmaxf(m, P[p] + q[p]);
    g_m1f[head][(size_t)t * HH + j] = m;
    __half hi = __float2half_rn(m);
    __half lo = __float2half_rn(m - __half2float(hi));
    unsigned short* row = g_m13[head] + (size_t)t * K3M;
    row[j] = __half_as_ushort(hi);         // seg0: hi
    row[200 + j] = __half_as_ushort(lo);   // seg1: lo
}

// ---------------- small per-iteration kernels ----------------
__global__ void k_gates(const float* __restrict__ U, const float* __restrict__ Wih,
                        const float* __restrict__ Whh, const float* __restrict__ bih,
                        const float* __restrict__ bhh)
{
    if (g_done) return;
    int w = (blockIdx.x * blockDim.x + threadIdx.x) >> 5;
    int lane = threadIdx.x & 31;
    if (w >= 4 * HH) return;
    const float* Us = U + (size_t)g_start * UD;
    const float* Ue = U + (size_t)g_end * UD;
    const float* wr = Wih + (size_t)w * 800;
    const float* hr = Whh + (size_t)w * HH;
    float s = 0.f;
    for (int k = lane; k < UD; k += 32) s = fmaf(Us[k], wr[k], s);
    for (int k = lane; k < UD; k += 32) s = fmaf(Ue[k], wr[400 + k], s);
    for (int k = lane; k < HH; k += 32) s = fmaf(g_h[k], hr[k], s);
    for (int off = 16; off; off >>= 1) s += __shfl_xor_sync(0xffffffffu, s, off);
    if (lane == 0) g_gates[w] = s + bih[w] + bhh[w];
}

__device__ __forceinline__ float sigm(float x) { return 1.f / (1.f + expf(-x)); }

__global__ void k_lstm_update() {
    if (g_done) return;
    int j = threadIdx.x;
    if (j < HH) {
        float i = sigm(g_gates[j]);
        float f = sigm(g_gates[HH + j]);
        float g = tanhf(g_gates[2 * HH + j]);
        float o = sigm(g_gates[3 * HH + j]);
        float cc = f * g_c[j] + i * g;
        float hc = o * tanhf(cc);
        g_hc[j] = hc;
        g_h[j] = hc;
        g_c[j] = cc;
    }
}

__global__ void k_r(const float* __restrict__ U,
                    const float* __restrict__ w1s, const float* __restrict__ w1e)
{
    if (g_done) return;
    int w = (blockIdx.x * blockDim.x + threadIdx.x) >> 5;
    int lane = threadIdx.x & 31;
    if (w >= 2 * HH) return;
    int head = w / HH;
    int j = w - head * HH;
    const float* row = (head ? w1e : w1s) + (size_t)j * 1000;
    const float* Us = U + (size_t)g_start * UD;
    const float* Ue = U + (size_t)g_end * UD;
    float s = 0.f;
    for (int k = lane; k < HH; k += 32) s = fmaf(g_hc[k], row[k], s);
    for (int k = lane; k < UD; k += 32) s = fmaf(Us[k], row[200 + k], s);
    for (int k = lane; k < UD; k += 32) s = fmaf(Ue[k], row[600 + k], s);
    for (int off = 16; off; off >>= 1) s += __shfl_xor_sync(0xffffffffu, s, off);
    if (lane == 0) g_r[head][j] = tanhf(s);
}

// q'[head][j*16+p] = r[head] @ w2[p*200+j, 400:600] + b2[p*200+j]
__global__ void k_q(const float* __restrict__ w2s, const float* __restrict__ b2s,
                    const float* __restrict__ w2e, const float* __restrict__ b2e)
{
    if (g_done) return;
    int w = (blockIdx.x * blockDim.x + threadIdx.x) >> 5;
    int lane = threadIdx.x & 31;
    if (w >= 2 * NP) return;
    int head = w / NP;
    int n = w - head * NP;
    int j = n >> 4, p = n & 15;
    int src = p * 200 + j;
    const float* row = (head ? w2e : w2s) + (size_t)src * 600 + 400;
    const float* b2 = head ? b2e : b2s;
    const float* r = g_r[head];
    float s = 0.f;
    for (int k = lane; k < HH; k += 32) s = fmaf(r[k], row[k], s);
    for (int off = 16; off; off >>= 1) s += __shfl_xor_sync(0xffffffffu, s, off);
    if (lane == 0) g_q[head][n] = s + b2[src];
}

// blockIdx.y = head
__global__ void k_fc4(const float* __restrict__ w4s, const float* __restrict__ b4s,
                      const float* __restrict__ w4e, const float* __restrict__ b4e,
                      float* __restrict__ out, int it)
{
    int head = blockIdx.y;
    const float* w4 = head ? w4e : w4s;
    const float* b4 = head ? b4e : b4s;
    float* outRow = out + (size_t)(head * 4 + it) * TN;
    int t = (blockIdx.x * blockDim.x + threadIdx.x) >> 5;
    int lane = threadIdx.x & 31;
    if (t >= TN) return;
    if (it > 0 && g_done) {
        if (lane == 0) outRow[t] = (outRow - TN)[t];
        return;
    }
    const float* m1r = g_m1f[head] + (size_t)t * HH;
    const float* m2r = g_m2f[head] + (size_t)t * HH;
    float acc[PL];
#pragma unroll
    for (int p = 0; p < PL; p++) acc[p] = 0.f;
    for (int k = lane; k < HH; k += 32) {
        float v1 = m1r[k], v2 = m2r[k];
#pragma unroll
        for (int p = 0; p < PL; p++) {
            acc[p] = fmaf(v1, w4[p * 400 + k], acc[p]);
            acc[p] = fmaf(v2, w4[p * 400 + 200 + k], acc[p]);
        }
    }
#pragma unroll
    for (int p = 0; p < PL; p++)
        for (int off = 16; off; off >>= 1)
            acc[p] += __shfl_xor_sync(0xffffffffu, acc[p], off);
    if (lane == 0) {
        float best = acc[0] + b4[0];
#pragma unroll
        for (int p = 1; p < PL; p++) best = fmaxf(best, acc[p] + b4[p]);
        outRow[t] = best;
    }
}

__global__ void k_update(const float* __restrict__ arow, const float* __restrict__ brow,
                         int it)
{
    if (it > 0 && g_done) return;
    __shared__ float sv[256];
    __shared__ int si[256];
    __shared__ int res[2];
    int tid = threadIdx.x;
    for (int pass = 0; pass < 2; pass++) {
        const float* row = pass ? brow : arow;
        float bv = -3.4e38f; int bi = 0;
        for (int t = tid; t < TN; t += 256) {
            float v = row[t];
            if (v > bv) { bv = v; bi = t; }
        }
        sv[tid] = bv; si[tid] = bi;
        __syncthreads();
        for (int s = 128; s; s >>= 1) {
            if (tid < s) {
                float ov = sv[tid + s]; int oi = si[tid + s];
                if (ov > sv[tid] || (ov == sv[tid] && oi < si[tid])) {
                    sv[tid] = ov; si[tid] = oi;
                }
            }
            __syncthreads();
        }
        if (tid == 0) res[pass] = si[0];
        __syncthreads();
    }
    if (tid == 0) {
        int ns = res[0], ne = res[1];
        if (it == 0) {
            g_start = ns; g_end = ne; g_done = 0;
        } else {
            int nd = (ns == g_start && ne == g_end);
            g_start = ns; g_end = ne;
            g_done = nd;
        }
    }
}

// ---------------------------------------------------------------------------
extern "C" void kernel_launch(void* const* d_in, const int* in_sizes, int n_in,
                              void* d_out, int out_size)
{
    const float* U        = (const float*)d_in[0];
    const float* lstm_Wih = (const float*)d_in[1];
    const float* lstm_Whh = (const float*)d_in[2];
    const float* lstm_bih = (const float*)d_in[3];
    const float* lstm_bhh = (const float*)d_in[4];
    const float* s_fc1w = (const float*)d_in[5];
    const float* s_fc2w = (const float*)d_in[6];
    const float* s_fc2b = (const float*)d_in[7];
    const float* s_fc3w = (const float*)d_in[8];
    const float* s_fc3b = (const float*)d_in[9];
    const float* s_fc4w = (const float*)d_in[10];
    const float* s_fc4b = (const float*)d_in[11];
    const float* e_fc1w = (const float*)d_in[12];
    const float* e_fc2w = (const float*)d_in[13];
    const float* e_fc2b = (const float*)d_in[14];
    const float* e_fc3w = (const float*)d_in[15];
    const float* e_fc3b = (const float*)d_in[16];
    const float* e_fc4w = (const float*)d_in[17];
    const float* e_fc4b = (const float*)d_in[18];
    float* out = (float*)d_out;   // [alphas 4*T | betas 4*T]

    cudaFuncSetAttribute(k_mma, cudaFuncAttributeMaxDynamicSharedMemorySize, SMEM_BYTES);

    dim3 ggrid(NP / BN, TN / BM, 2);   // 25 x 128 x 2 heads

    // launches 0..4, then launch #5 (profiled by ncu -s 5 -c 1) = dual-head precompute
    k_init<<<1, 256>>>();
    k_convU3<<<(TN * K3U + 255) / 256, 256>>>(U);
    k_convB23<<<(NP * K3U + 255) / 256, 256>>>(s_fc2w, 0);
    k_convB23<<<(NP * K3U + 255) / 256, 256>>>(e_fc2w, 1);
    k_zero13<<<(TN * 96 + 255) / 256, 256>>>();
    k_mma<<<ggrid, 256, SMEM_BYTES>>>(0);
    k_convB33<<<(NP * K3M + 255) / 256, 256>>>(s_fc3w, s_fc3b, 0);
    k_convB33<<<(NP * K3M + 255) / 256, 256>>>(e_fc3w, e_fc3b, 1);

    dim3 pgrid((TN * HH + 255) / 256, 2);
    dim3 fgrid((TN * 32) / 256, 2);

    for (int it = 0; it < 4; it++) {
        k_gates<<<100, 256>>>(U, lstm_Wih, lstm_Whh, lstm_bih, lstm_bhh);
        k_lstm_update<<<1, 256>>>();
        k_r<<<50, 256>>>(U, s_fc1w, e_fc1w);
        k_q<<<800, 256>>>(s_fc2w, s_fc2b, e_fc2w, e_fc2b);
        k_pool1<<<pgrid, 256>>>();
        k_mma<<<ggrid, 256, SMEM_BYTES>>>(1);
        k_fc4<<<fgrid, 256>>>(s_fc4w, s_fc4b, e_fc4w, e_fc4b, out, it);
        k_update<<<1, 256>>>(out + (size_t)it * TN, out + (size_t)(4 + it) * TN, it);
    }
}

// round 11
// speedup vs baseline: 1.4187x; 1.0982x over previous
#include <cuda_runtime.h>
#include <cuda_bf16.h>
#include <cuda_fp16.h>
#include <math.h>
#include <stdint.h>

#define TN 16384
#define HH 200
#define PL 16
#define NP 3200
#define UD 400
#define K3U 832      // fp16 2-term: [0,400) Uhi*w2hi | [400,800) Ulo*w2hi | pad 32
#define K3M 448      // fp16 2-term: [0,200) m1hi*w3hi | [200,400) m1lo*w3hi | pad 48
#define BM 128
#define BN 128
#define BK 64
#define NSTG 3

// ---------------- static device scratch ----------------
__device__ float g_Ps[(size_t)TN * NP];
__device__ float g_Pe[(size_t)TN * NP];
__device__ unsigned short g_U3[(size_t)TN * K3U];      // fp16 [Uhi | Ulo | 0]
__device__ unsigned short g_B23[2][(size_t)NP * K3U];  // fp16 [w2hi | w2hi | 0], n permuted
__device__ unsigned short g_B33[2][(size_t)NP * K3M];  // fp16 [w3hi | w3hi | 0], n permuted
__device__ unsigned short g_m13[2][(size_t)TN * K3M];  // fp16 [m1hi | m1lo | 0]
__device__ float g_b3p[2][NP];
__device__ float g_m1f[2][(size_t)TN * HH];
__device__ float g_m2f[2][(size_t)TN * HH];
__device__ float g_h[HH], g_c[HH], g_hc[HH];
__device__ float g_gates[4 * HH];
__device__ float g_r[2][HH];
__device__ float g_q[2][NP];
__device__ int g_start, g_end, g_done;

// ---------------- ptx helpers ----------------
__device__ __forceinline__ uint32_t smem_u32(const void* p) {
    uint32_t a;
    asm("{ .reg .u64 t; cvta.to.shared.u64 t, %1; cvt.u32.u64 %0, t; }" : "=r"(a) : "l"(p));
    return a;
}
__device__ __forceinline__ void ldm_x4(uint32_t* r, uint32_t a) {
    asm volatile("ldmatrix.sync.aligned.m8n8.x4.shared.b16 {%0,%1,%2,%3}, [%4];"
                 : "=r"(r[0]), "=r"(r[1]), "=r"(r[2]), "=r"(r[3]) : "r"(a));
}
__device__ __forceinline__ void mma_fp(float* c, const uint32_t* a, const uint32_t* b) {
    asm volatile(
        "mma.sync.aligned.m16n8k16.row.col.f32.f16.f16.f32 "
        "{%0,%1,%2,%3}, {%4,%5,%6,%7}, {%8,%9}, {%0,%1,%2,%3};"
        : "+f"(c[0]), "+f"(c[1]), "+f"(c[2]), "+f"(c[3])
        : "r"(a[0]), "r"(a[1]), "r"(a[2]), "r"(a[3]), "r"(b[0]), "r"(b[1]));
}
__device__ __forceinline__ void cp16(uint32_t dst, const void* src) {
    asm volatile("cp.async.cg.shared.global [%0], [%1], 16;" :: "r"(dst), "l"(src));
}
__device__ __forceinline__ void cp_commit() {
    asm volatile("cp.async.commit_group;" ::: "memory");
}
__device__ __forceinline__ void cp_wait1() {
    asm volatile("cp.async.wait_group 1;" ::: "memory");
}

// ---------------- conversion kernels ----------------
// U fp16 hi/lo: seg0 hi, seg1 lo, pad [800,832)
__global__ void k_convU3(const float* __restrict__ U) {
    size_t idx = (size_t)blockIdx.x * blockDim.x + threadIdx.x;
    if (idx >= (size_t)TN * K3U) return;
    int k = (int)(idx % K3U);
    size_t t = idx / K3U;
    int seg = k / 400, kk = k - seg * 400;
    unsigned short o = 0;
    if (seg < 2) {
        float v = U[t * UD + kk];
        __half hi = __float2half_rn(v);
        o = __half_as_ushort(seg ? __float2half_rn(v - __half2float(hi)) : hi);
    }
    g_U3[idx] = o;
}
// fc2 weight fp16 (first 400 cols), hi in both segs, n permuted: n=j*16+p <- p*200+j
__global__ void k_convB23(const float* __restrict__ w2, int head) {
    size_t idx = (size_t)blockIdx.x * blockDim.x + threadIdx.x;
    if (idx >= (size_t)NP * K3U) return;
    int k = (int)(idx % K3U);
    int n = (int)(idx / K3U);
    int j = n >> 4, p = n & 15;
    int seg = k / 400, kk = k - seg * 400;
    unsigned short o = 0;
    if (seg < 2) {
        float v = w2[(size_t)(p * 200 + j) * 600 + kk];
        o = __half_as_ushort(__float2half_rn(v));
    }
    g_B23[head][idx] = o;
}
// fc3 weight fp16, n permuted. w3hi at segs 0 and 1, tail [400,448) zero.
__global__ void k_convB33(const float* __restrict__ w3, const float* __restrict__ b3, int head) {
    size_t idx = (size_t)blockIdx.x * blockDim.x + threadIdx.x;
    if (idx >= (size_t)NP * K3M) return;
    int k = (int)(idx % K3M);
    int n = (int)(idx / K3M);
    int j = n >> 4, p = n & 15;
    int src = p * 200 + j;
    int seg = k / 200;               // 0,1 data; 2 = tail
    int kk = k - seg * 200;
    unsigned short o = 0;
    if (seg < 2) {
        float v = w3[(size_t)src * HH + kk];
        o = __half_as_ushort(__float2half_rn(v));
    }
    g_B33[head][idx] = o;
    if (k == 0) g_b3p[head][n] = b3[src];
}
__global__ void k_zero13() {   // zero m13 tails [400,448) once, both heads
    int idx = blockIdx.x * blockDim.x + threadIdx.x;
    int h = idx & 1;
    int r = idx >> 1;
    int t = r / 48, k = r - (r / 48) * 48;
    if (t < TN) g_m13[h][(size_t)t * K3M + 400 + k] = 0;
}
__global__ void k_init() {
    int j = threadIdx.x;
    if (j < HH) { g_h[j] = 0.f; g_c[j] = 0.f; }
    if (j == 0) { g_start = 0; g_end = 0; g_done = 0; }
}

// ---------------- HMMA GEMM (cp.async 3-stage, 32x64 warp tile, head=z) ----------
// mode 0: C[TN,NP] = U3 @ B23[head]^T -> fp32 g_Ps/g_Pe                 (NC=13)
// mode 1: fused fc3: maxpool16(m13 @ B33[head]^T + bias) -> g_m2f[head] (NC=7)
#define SMEM_STAGE 32768      // A 16KB + B 16KB
#define SMEM_BYTES (NSTG * SMEM_STAGE)

__global__ void __launch_bounds__(256) k_mma(int mode) {
    if (mode == 1 && g_done) return;
    extern __shared__ char smem[];
    __shared__ float s_bias[BN];
    const uint32_t sb = smem_u32(smem);
    const int tid = threadIdx.x;
    const int head = blockIdx.z;
    const int wid = tid >> 5, lane = tid & 31;
    const int wm = wid >> 1, wn = wid & 1;          // warp tile origin (4m x 2n)
    const int bm = blockIdx.y * BM, bn = blockIdx.x * BN;
    const int K3 = mode ? K3M : K3U;
    const int NC = K3 / BK;
    const unsigned short* A = mode ? g_m13[head] : g_U3;
    const unsigned short* B = mode ? g_B33[head] : g_B23[head];

    if (mode == 1 && tid < BN) s_bias[tid] = g_b3p[head][bn + tid];

    const int lrow = tid >> 1;          // 0..127
    const int lseg = tid & 1;           // 64B half of the 128B row
    const unsigned short* gA = A + (size_t)(bm + lrow) * K3 + lseg * 32;
    const unsigned short* gB = B + (size_t)(bn + lrow) * K3 + lseg * 32;

    uint32_t soff[4];
#pragma unroll
    for (int i = 0; i < 4; i++) {
        uint32_t off = (uint32_t)lrow * 128 + lseg * 64 + i * 16;
        soff[i] = off ^ ((off >> 3) & 0x70);
    }

#define ISSUE(c)                                                       \
    {                                                                  \
        const uint32_t st = sb + ((c) % NSTG) * SMEM_STAGE;            \
        const int k0 = (c) * BK;                                       \
        _Pragma("unroll")                                              \
        for (int i = 0; i < 4; i++) {                                  \
            cp16(st + soff[i], gA + k0 + i * 8);                       \
            cp16(st + 16384 + soff[i], gB + k0 + i * 8);               \
        }                                                              \
    }

    float acc[2][8][4];
#pragma unroll
    for (int i = 0; i < 2; i++)
#pragma unroll
        for (int j = 0; j < 8; j++)
#pragma unroll
            for (int q = 0; q < 4; q++) acc[i][j][q] = 0.f;

    ISSUE(0); cp_commit();
    ISSUE(1); cp_commit();

    for (int c = 0; c < NC; c++) {
        cp_wait1();
        __syncthreads();
        if (c + 2 < NC) ISSUE(c + 2);
        cp_commit();                         // empty group in tail keeps counting aligned

        const uint32_t base = sb + (c % NSTG) * SMEM_STAGE;
#pragma unroll
        for (int kk = 0; kk < 4; kk++) {
            uint32_t af[2][4];
#pragma unroll
            for (int i = 0; i < 2; i++) {
                uint32_t off = (uint32_t)(wm * 32 + i * 16 + (lane & 15)) * 128
                             + kk * 32 + ((lane >> 4) & 1) * 16;
                uint32_t sw = off ^ ((off >> 3) & 0x70);
                ldm_x4(af[i], base + sw);
            }
            uint32_t bf[4][4];
#pragma unroll
            for (int j = 0; j < 4; j++) {
                uint32_t nrow = wn * 64 + j * 16 + (lane & 7) + ((lane >> 4) & 1) * 8;
                uint32_t off = nrow * 128 + kk * 32 + ((lane >> 3) & 1) * 16;
                uint32_t sw = off ^ ((off >> 3) & 0x70);
                ldm_x4(bf[j], base + 16384 + sw);
            }
#pragma unroll
            for (int i = 0; i < 2; i++)
#pragma unroll
                for (int j = 0; j < 4; j++) {
                    mma_fp(acc[i][2 * j], af[i], &bf[j][0]);
                    mma_fp(acc[i][2 * j + 1], af[i], &bf[j][2]);
                }
        }
    }
#undef ISSUE

    // ---------------- epilogue ----------------
    if (mode == 0) {
        float* C = head ? g_Pe : g_Ps;
        const int r0 = bm + wm * 32, n0 = bn + wn * 64;
#pragma unroll
        for (int i = 0; i < 2; i++)
#pragma unroll
            for (int jt = 0; jt < 8; jt++) {
                int row = r0 + i * 16 + (lane >> 2);
                int col = n0 + jt * 8 + (lane & 3) * 2;
                *(float2*)(C + (size_t)row * NP + col) =
                    make_float2(acc[i][jt][0], acc[i][jt][1]);
                *(float2*)(C + (size_t)(row + 8) * NP + col) =
                    make_float2(acc[i][jt][2], acc[i][jt][3]);
            }
    } else {
        const int r0 = bm + wm * 32;
        const int j0 = (bn >> 4) + wn * 4;
        float* m2 = g_m2f[head];
#pragma unroll
        for (int i = 0; i < 2; i++)
#pragma unroll
            for (int g = 0; g < 4; g++) {
                int nb = wn * 64 + g * 16 + (lane & 3) * 2;
                float b0 = s_bias[nb], b1 = s_bias[nb + 1];
                float b2 = s_bias[nb + 8], b3 = s_bias[nb + 9];
                float v0 = fmaxf(fmaxf(acc[i][2 * g][0] + b0, acc[i][2 * g][1] + b1),
                                 fmaxf(acc[i][2 * g + 1][0] + b2, acc[i][2 * g + 1][1] + b3));
                float v1 = fmaxf(fmaxf(acc[i][2 * g][2] + b0, acc[i][2 * g][3] + b1),
                                 fmaxf(acc[i][2 * g + 1][2] + b2, acc[i][2 * g + 1][3] + b3));
                v0 = fmaxf(v0, __shfl_xor_sync(0xffffffffu, v0, 1));
                v0 = fmaxf(v0, __shfl_xor_sync(0xffffffffu, v0, 2));
                v1 = fmaxf(v1, __shfl_xor_sync(0xffffffffu, v1, 1));
                v1 = fmaxf(v1, __shfl_xor_sync(0xffffffffu, v1, 2));
                if ((lane & 3) == 0) {
                    int row = r0 + i * 16 + (lane >> 2);
                    m2[(size_t)row * HH + j0 + g] = v0;
                    m2[(size_t)(row + 8) * HH + j0 + g] = v1;
                }
            }
    }
}

// ---------------- m1 pool: P + q -> max16 -> m1f (fp32) + m13 (fp16 hi/lo) ----
// blockIdx.y = head
__global__ void k_pool1() {
    if (g_done) return;
    int head = blockIdx.y;
    int idx = blockIdx.x * blockDim.x + threadIdx.x;
    int t = idx / HH;
    int j = idx - t * HH;
    if (t >= TN) return;
    const float* P = (head ? g_Pe : g_Ps) + (size_t)t * NP + j * 16;
    const float* q = g_q[head] + j * 16;
    float m = P[0] + q[0];
#pragma unroll
    for (int p = 1; p < PL; p++) m = fmaxf(m, P[p] + q[p]);
    g_m1f[head][(size_t)t * HH + j] = m;
    __half hi = __float2half_rn(m);
    __half lo = __float2half_rn(m - __half2float(hi));
    unsigned short* row = g_m13[head] + (size_t)t * K3M;
    row[j] = __half_as_ushort(hi);         // seg0: hi
    row[200 + j] = __half_as_ushort(lo);   // seg1: lo
}

// ---------------- small per-iteration kernels ----------------
__global__ void k_gates(const float* __restrict__ U, const float* __restrict__ Wih,
                        const float* __restrict__ Whh, const float* __restrict__ bih,
                        const float* __restrict__ bhh)
{
    if (g_done) return;
    int w = (blockIdx.x * blockDim.x + threadIdx.x) >> 5;
    int lane = threadIdx.x & 31;
    if (w >= 4 * HH) return;
    const float* Us = U + (size_t)g_start * UD;
    const float* Ue = U + (size_t)g_end * UD;
    const float* wr = Wih + (size_t)w * 800;
    const float* hr = Whh + (size_t)w * HH;
    float s = 0.f;
    for (int k = lane; k < UD; k += 32) s = fmaf(Us[k], wr[k], s);
    for (int k = lane; k < UD; k += 32) s = fmaf(Ue[k], wr[400 + k], s);
    for (int k = lane; k < HH; k += 32) s = fmaf(g_h[k], hr[k], s);
    for (int off = 16; off; off >>= 1) s += __shfl_xor_sync(0xffffffffu, s, off);
    if (lane == 0) g_gates[w] = s + bih[w] + bhh[w];
}

__device__ __forceinline__ float sigm(float x) { return 1.f / (1.f + expf(-x)); }

__global__ void k_lstm_update() {
    if (g_done) return;
    int j = threadIdx.x;
    if (j < HH) {
        float i = sigm(g_gates[j]);
        float f = sigm(g_gates[HH + j]);
        float g = tanhf(g_gates[2 * HH + j]);
        float o = sigm(g_gates[3 * HH + j]);
        float cc = f * g_c[j] + i * g;
        float hc = o * tanhf(cc);
        g_hc[j] = hc;
        g_h[j] = hc;
        g_c[j] = cc;
    }
}

__global__ void k_r(const float* __restrict__ U,
                    const float* __restrict__ w1s, const float* __restrict__ w1e)
{
    if (g_done) return;
    int w = (blockIdx.x * blockDim.x + threadIdx.x) >> 5;
    int lane = threadIdx.x & 31;
    if (w >= 2 * HH) return;
    int head = w / HH;
    int j = w - head * HH;
    const float* row = (head ? w1e : w1s) + (size_t)j * 1000;
    const float* Us = U + (size_t)g_start * UD;
    const float* Ue = U + (size_t)g_end * UD;
    float s = 0.f;
    for (int k = lane; k < HH; k += 32) s = fmaf(g_hc[k], row[k], s);
    for (int k = lane; k < UD; k += 32) s = fmaf(Us[k], row[200 + k], s);
    for (int k = lane; k < UD; k += 32) s = fmaf(Ue[k], row[600 + k], s);
    for (int off = 16; off; off >>= 1) s += __shfl_xor_sync(0xffffffffu, s, off);
    if (lane == 0) g_r[head][j] = tanhf(s);
}

// q'[head][j*16+p] = r[head] @ w2[p*200+j, 400:600] + b2[p*200+j]
__global__ void k_q(const float* __restrict__ w2s, const float* __restrict__ b2s,
                    const float* __restrict__ w2e, const float* __restrict__ b2e)
{
    if (g_done) return;
    int w = (blockIdx.x * blockDim.x + threadIdx.x) >> 5;
    int lane = threadIdx.x & 31;
    if (w >= 2 * NP) return;
    int head = w / NP;
    int n = w - head * NP;
    int j = n >> 4, p = n & 15;
    int src = p * 200 + j;
    const float* row = (head ? w2e : w2s) + (size_t)src * 600 + 400;
    const float* b2 = head ? b2e : b2s;
    const float* r = g_r[head];
    float s = 0.f;
    for (int k = lane; k < HH; k += 32) s = fmaf(r[k], row[k], s);
    for (int off = 16; off; off >>= 1) s += __shfl_xor_sync(0xffffffffu, s, off);
    if (lane == 0) g_q[head][n] = s + b2[src];
}

// blockIdx.y = head
__global__ void k_fc4(const float* __restrict__ w4s, const float* __restrict__ b4s,
                      const float* __restrict__ w4e, const float* __restrict__ b4e,
                      float* __restrict__ out, int it)
{
    int head = blockIdx.y;
    const float* w4 = head ? w4e : w4s;
    const float* b4 = head ? b4e : b4s;
    float* outRow = out + (size_t)(head * 4 + it) * TN;
    int t = (blockIdx.x * blockDim.x + threadIdx.x) >> 5;
    int lane = threadIdx.x & 31;
    if (t >= TN) return;
    if (it > 0 && g_done) {
        if (lane == 0) outRow[t] = (outRow - TN)[t];
        return;
    }
    const float* m1r = g_m1f[head] + (size_t)t * HH;
    const float* m2r = g_m2f[head] + (size_t)t * HH;
    float acc[PL];
#pragma unroll
    for (int p = 0; p < PL; p++) acc[p] = 0.f;
    for (int k = lane; k < HH; k += 32) {
        float v1 = m1r[k], v2 = m2r[k];
#pragma unroll
        for (int p = 0; p < PL; p++) {
            acc[p] = fmaf(v1, w4[p * 400 + k], acc[p]);
            acc[p] = fmaf(v2, w4[p * 400 + 200 + k], acc[p]);
        }
    }
#pragma unroll
    for (int p = 0; p < PL; p++)
        for (int off = 16; off; off >>= 1)
            acc[p] += __shfl_xor_sync(0xffffffffu, acc[p], off);
    if (lane == 0) {
        float best = acc[0] + b4[0];
#pragma unroll
        for (int p = 1; p < PL; p++) best = fmaxf(best, acc[p] + b4[p]);
        outRow[t] = best;
    }
}

__global__ void k_update(const float* __restrict__ arow, const float* __restrict__ brow,
                         int it)
{
    if (it > 0 && g_done) return;
    __shared__ float sv[256];
    __shared__ int si[256];
    __shared__ int res[2];
    int tid = threadIdx.x;
    for (int pass = 0; pass < 2; pass++) {
        const float* row = pass ? brow : arow;
        float bv = -3.4e38f; int bi = 0;
        for (int t = tid; t < TN; t += 256) {
            float v = row[t];
            if (v > bv) { bv = v; bi = t; }
        }
        sv[tid] = bv; si[tid] = bi;
        __syncthreads();
        for (int s = 128; s; s >>= 1) {
            if (tid < s) {
                float ov = sv[tid + s]; int oi = si[tid + s];
                if (ov > sv[tid] || (ov == sv[tid] && oi < si[tid])) {
                    sv[tid] = ov; si[tid] = oi;
                }
            }
            __syncthreads();
        }
        if (tid == 0) res[pass] = si[0];
        __syncthreads();
    }
    if (tid == 0) {
        int ns = res[0], ne = res[1];
        if (it == 0) {
            g_start = ns; g_end = ne; g_done = 0;
        } else {
            int nd = (ns == g_start && ne == g_end);
            g_start = ns; g_end = ne;
            g_done = nd;
        }
    }
}

// ---------------------------------------------------------------------------
extern "C" void kernel_launch(void* const* d_in, const int* in_sizes, int n_in,
                              void* d_out, int out_size)
{
    const float* U        = (const float*)d_in[0];
    const float* lstm_Wih = (const float*)d_in[1];
    const float* lstm_Whh = (const float*)d_in[2];
    const float* lstm_bih = (const float*)d_in[3];
    const float* lstm_bhh = (const float*)d_in[4];
    const float* s_fc1w = (const float*)d_in[5];
    const float* s_fc2w = (const float*)d_in[6];
    const float* s_fc2b = (const float*)d_in[7];
    const float* s_fc3w = (const float*)d_in[8];
    const float* s_fc3b = (const float*)d_in[9];
    const float* s_fc4w = (const float*)d_in[10];
    const float* s_fc4b = (const float*)d_in[11];
    const float* e_fc1w = (const float*)d_in[12];
    const float* e_fc2w = (const float*)d_in[13];
    const float* e_fc2b = (const float*)d_in[14];
    const float* e_fc3w = (const float*)d_in[15];
    const float* e_fc3b = (const float*)d_in[16];
    const float* e_fc4w = (const float*)d_in[17];
    const float* e_fc4b = (const float*)d_in[18];
    float* out = (float*)d_out;   // [alphas 4*T | betas 4*T]

    cudaFuncSetAttribute(k_mma, cudaFuncAttributeMaxDynamicSharedMemorySize, SMEM_BYTES);

    dim3 ggrid(NP / BN, TN / BM, 2);   // 25 x 128 x 2 heads

    // launches 0..4, then launch #5 (profiled by ncu -s 5 -c 1) = dual-head precompute
    k_init<<<1, 256>>>();
    k_convU3<<<(TN * K3U + 255) / 256, 256>>>(U);
    k_convB23<<<(NP * K3U + 255) / 256, 256>>>(s_fc2w, 0);
    k_convB23<<<(NP * K3U + 255) / 256, 256>>>(e_fc2w, 1);
    k_zero13<<<(TN * 96 + 255) / 256, 256>>>();
    k_mma<<<ggrid, 256, SMEM_BYTES>>>(0);
    k_convB33<<<(NP * K3M + 255) / 256, 256>>>(s_fc3w, s_fc3b, 0);
    k_convB33<<<(NP * K3M + 255) / 256, 256>>>(e_fc3w, e_fc3b, 1);

    dim3 pgrid((TN * HH + 255) / 256, 2);
    dim3 fgrid((TN * 32) / 256, 2);

    for (int it = 0; it < 4; it++) {
        k_gates<<<100, 256>>>(U, lstm_Wih, lstm_Whh, lstm_bih, lstm_bhh);
        k_lstm_update<<<1, 256>>>();
        k_r<<<50, 256>>>(U, s_fc1w, e_fc1w);
        k_q<<<800, 256>>>(s_fc2w, s_fc2b, e_fc2w, e_fc2b);
        k_pool1<<<pgrid, 256>>>();
        k_mma<<<ggrid, 256, SMEM_BYTES>>>(1);
        k_fc4<<<fgrid, 256>>>(s_fc4w, s_fc4b, e_fc4w, e_fc4b, out, it);
        k_update<<<1, 256>>>(out + (size_t)it * TN, out + (size_t)(4 + it) * TN, it);
    }
}

// round 12
// speedup vs baseline: 1.6565x; 1.1676x over previous
#include <cuda_runtime.h>
#include <cuda_bf16.h>
#include <cuda_fp16.h>
#include <math.h>
#include <stdint.h>

#define TN 16384
#define HH 200
#define PL 16
#define NP 3200
#define UD 400
#define K3U 832      // fp16 2-term: [0,400) Uhi*w2hi | [400,800) Ulo*w2hi | pad 32
#define K3M 256      // fp16 1-term: [0,200) m1hi*w3hi | pad 56
#define BM 128
#define BN 128
#define BK 64
#define NSTG 3

// ---------------- static device scratch ----------------
__device__ float g_Ps[(size_t)TN * NP];
__device__ float g_Pe[(size_t)TN * NP];
__device__ unsigned short g_U3[(size_t)TN * K3U];      // fp16 [Uhi | Ulo | 0]
__device__ unsigned short g_B23[2][(size_t)NP * K3U];  // fp16 [w2hi | w2hi | 0], n permuted
__device__ unsigned short g_B33[2][(size_t)NP * K3M];  // fp16 [w3hi | 0], n permuted
__device__ unsigned short g_m13[2][(size_t)TN * K3M];  // fp16 [m1hi | 0]
__device__ float g_b3p[2][NP];
__device__ float g_m1f[2][(size_t)TN * HH];
__device__ float g_m2f[2][(size_t)TN * HH];
__device__ float g_h[HH], g_c[HH], g_hc[HH];
__device__ float g_gates[4 * HH];
__device__ float g_r[2][HH];
__device__ float g_q[2][NP];
__device__ int g_start, g_end, g_done;

// ---------------- ptx helpers ----------------
__device__ __forceinline__ uint32_t smem_u32(const void* p) {
    uint32_t a;
    asm("{ .reg .u64 t; cvta.to.shared.u64 t, %1; cvt.u32.u64 %0, t; }" : "=r"(a) : "l"(p));
    return a;
}
__device__ __forceinline__ void ldm_x4(uint32_t* r, uint32_t a) {
    asm volatile("ldmatrix.sync.aligned.m8n8.x4.shared.b16 {%0,%1,%2,%3}, [%4];"
                 : "=r"(r[0]), "=r"(r[1]), "=r"(r[2]), "=r"(r[3]) : "r"(a));
}
__device__ __forceinline__ void mma_fp(float* c, const uint32_t* a, const uint32_t* b) {
    asm volatile(
        "mma.sync.aligned.m16n8k16.row.col.f32.f16.f16.f32 "
        "{%0,%1,%2,%3}, {%4,%5,%6,%7}, {%8,%9}, {%0,%1,%2,%3};"
        : "+f"(c[0]), "+f"(c[1]), "+f"(c[2]), "+f"(c[3])
        : "r"(a[0]), "r"(a[1]), "r"(a[2]), "r"(a[3]), "r"(b[0]), "r"(b[1]));
}
__device__ __forceinline__ void cp16(uint32_t dst, const void* src) {
    asm volatile("cp.async.cg.shared.global [%0], [%1], 16;" :: "r"(dst), "l"(src));
}
__device__ __forceinline__ void cp_commit() {
    asm volatile("cp.async.commit_group;" ::: "memory");
}
__device__ __forceinline__ void cp_wait1() {
    asm volatile("cp.async.wait_group 1;" ::: "memory");
}

// ---------------- conversion kernels ----------------
// U fp16 hi/lo: seg0 hi, seg1 lo, pad [800,832)
__global__ void k_convU3(const float* __restrict__ U) {
    size_t idx = (size_t)blockIdx.x * blockDim.x + threadIdx.x;
    if (idx >= (size_t)TN * K3U) return;
    int k = (int)(idx % K3U);
    size_t t = idx / K3U;
    int seg = k / 400, kk = k - seg * 400;
    unsigned short o = 0;
    if (seg < 2) {
        float v = U[t * UD + kk];
        __half hi = __float2half_rn(v);
        o = __half_as_ushort(seg ? __float2half_rn(v - __half2float(hi)) : hi);
    }
    g_U3[idx] = o;
}
// fc2 weight fp16 (first 400 cols), hi in both segs, n permuted: n=j*16+p <- p*200+j
__global__ void k_convB23(const float* __restrict__ w2, int head) {
    size_t idx = (size_t)blockIdx.x * blockDim.x + threadIdx.x;
    if (idx >= (size_t)NP * K3U) return;
    int k = (int)(idx % K3U);
    int n = (int)(idx / K3U);
    int j = n >> 4, p = n & 15;
    int seg = k / 400, kk = k - seg * 400;
    unsigned short o = 0;
    if (seg < 2) {
        float v = w2[(size_t)(p * 200 + j) * 600 + kk];
        o = __half_as_ushort(__float2half_rn(v));
    }
    g_B23[head][idx] = o;
}
// fc3 weight fp16, n permuted. [0,200) w3hi, [200,256) zero.
__global__ void k_convB33(const float* __restrict__ w3, const float* __restrict__ b3, int head) {
    size_t idx = (size_t)blockIdx.x * blockDim.x + threadIdx.x;
    if (idx >= (size_t)NP * K3M) return;
    int k = (int)(idx % K3M);
    int n = (int)(idx / K3M);
    int j = n >> 4, p = n & 15;
    int src = p * 200 + j;
    unsigned short o = 0;
    if (k < HH) {
        float v = w3[(size_t)src * HH + k];
        o = __half_as_ushort(__float2half_rn(v));
    }
    g_B33[head][idx] = o;
    if (k == 0) g_b3p[head][n] = b3[src];
}
__global__ void k_zero13() {   // zero m13 tails [200,256) once, both heads
    int idx = blockIdx.x * blockDim.x + threadIdx.x;
    int h = idx & 1;
    int r = idx >> 1;
    int t = r / 56, k = r - (r / 56) * 56;
    if (t < TN) g_m13[h][(size_t)t * K3M + 200 + k] = 0;
}
__global__ void k_init() {
    int j = threadIdx.x;
    if (j < HH) { g_h[j] = 0.f; g_c[j] = 0.f; }
    if (j == 0) { g_start = 0; g_end = 0; g_done = 0; }
}

// ---------------- HMMA GEMM (cp.async 3-stage, 32x64 warp tile, head=z) ----------
// mode 0: C[TN,NP] = U3 @ B23[head]^T -> fp32 g_Ps/g_Pe                 (NC=13)
// mode 1: fused fc3: maxpool16(m13 @ B33[head]^T + bias) -> g_m2f[head] (NC=4)
#define SMEM_STAGE 32768      // A 16KB + B 16KB
#define SMEM_BYTES (NSTG * SMEM_STAGE)

__global__ void __launch_bounds__(256) k_mma(int mode) {
    if (mode == 1 && g_done) return;
    extern __shared__ char smem[];
    __shared__ float s_bias[BN];
    const uint32_t sb = smem_u32(smem);
    const int tid = threadIdx.x;
    const int head = blockIdx.z;
    const int wid = tid >> 5, lane = tid & 31;
    const int wm = wid >> 1, wn = wid & 1;          // warp tile origin (4m x 2n)
    const int bm = blockIdx.y * BM, bn = blockIdx.x * BN;
    const int K3 = mode ? K3M : K3U;
    const int NC = K3 / BK;
    const unsigned short* A = mode ? g_m13[head] : g_U3;
    const unsigned short* B = mode ? g_B33[head] : g_B23[head];

    if (mode == 1 && tid < BN) s_bias[tid] = g_b3p[head][bn + tid];

    const int lrow = tid >> 1;          // 0..127
    const int lseg = tid & 1;           // 64B half of the 128B row
    const unsigned short* gA = A + (size_t)(bm + lrow) * K3 + lseg * 32;
    const unsigned short* gB = B + (size_t)(bn + lrow) * K3 + lseg * 32;

    uint32_t soff[4];
#pragma unroll
    for (int i = 0; i < 4; i++) {
        uint32_t off = (uint32_t)lrow * 128 + lseg * 64 + i * 16;
        soff[i] = off ^ ((off >> 3) & 0x70);
    }

#define ISSUE(c)                                                       \
    {                                                                  \
        const uint32_t st = sb + ((c) % NSTG) * SMEM_STAGE;            \
        const int k0 = (c) * BK;                                       \
        _Pragma("unroll")                                              \
        for (int i = 0; i < 4; i++) {                                  \
            cp16(st + soff[i], gA + k0 + i * 8);                       \
            cp16(st + 16384 + soff[i], gB + k0 + i * 8);               \
        }                                                              \
    }

    float acc[2][8][4];
#pragma unroll
    for (int i = 0; i < 2; i++)
#pragma unroll
        for (int j = 0; j < 8; j++)
#pragma unroll
            for (int q = 0; q < 4; q++) acc[i][j][q] = 0.f;

    ISSUE(0); cp_commit();
    ISSUE(1); cp_commit();

    for (int c = 0; c < NC; c++) {
        cp_wait1();
        __syncthreads();
        if (c + 2 < NC) ISSUE(c + 2);
        cp_commit();                         // empty group in tail keeps counting aligned

        const uint32_t base = sb + (c % NSTG) * SMEM_STAGE;
#pragma unroll
        for (int kk = 0; kk < 4; kk++) {
            uint32_t af[2][4];
#pragma unroll
            for (int i = 0; i < 2; i++) {
                uint32_t off = (uint32_t)(wm * 32 + i * 16 + (lane & 15)) * 128
                             + kk * 32 + ((lane >> 4) & 1) * 16;
                uint32_t sw = off ^ ((off >> 3) & 0x70);
                ldm_x4(af[i], base + sw);
            }
            uint32_t bf[4][4];
#pragma unroll
            for (int j = 0; j < 4; j++) {
                uint32_t nrow = wn * 64 + j * 16 + (lane & 7) + ((lane >> 4) & 1) * 8;
                uint32_t off = nrow * 128 + kk * 32 + ((lane >> 3) & 1) * 16;
                uint32_t sw = off ^ ((off >> 3) & 0x70);
                ldm_x4(bf[j], base + 16384 + sw);
            }
#pragma unroll
            for (int i = 0; i < 2; i++)
#pragma unroll
                for (int j = 0; j < 4; j++) {
                    mma_fp(acc[i][2 * j], af[i], &bf[j][0]);
                    mma_fp(acc[i][2 * j + 1], af[i], &bf[j][2]);
                }
        }
    }
#undef ISSUE

    // ---------------- epilogue ----------------
    if (mode == 0) {
        float* C = head ? g_Pe : g_Ps;
        const int r0 = bm + wm * 32, n0 = bn + wn * 64;
#pragma unroll
        for (int i = 0; i < 2; i++)
#pragma unroll
            for (int jt = 0; jt < 8; jt++) {
                int row = r0 + i * 16 + (lane >> 2);
                int col = n0 + jt * 8 + (lane & 3) * 2;
                *(float2*)(C + (size_t)row * NP + col) =
                    make_float2(acc[i][jt][0], acc[i][jt][1]);
                *(float2*)(C + (size_t)(row + 8) * NP + col) =
                    make_float2(acc[i][jt][2], acc[i][jt][3]);
            }
    } else {
        const int r0 = bm + wm * 32;
        const int j0 = (bn >> 4) + wn * 4;
        float* m2 = g_m2f[head];
#pragma unroll
        for (int i = 0; i < 2; i++)
#pragma unroll
            for (int g = 0; g < 4; g++) {
                int nb = wn * 64 + g * 16 + (lane & 3) * 2;
                float b0 = s_bias[nb], b1 = s_bias[nb + 1];
                float b2 = s_bias[nb + 8], b3 = s_bias[nb + 9];
                float v0 = fmaxf(fmaxf(acc[i][2 * g][0] + b0, acc[i][2 * g][1] + b1),
                                 fmaxf(acc[i][2 * g + 1][0] + b2, acc[i][2 * g + 1][1] + b3));
                float v1 = fmaxf(fmaxf(acc[i][2 * g][2] + b0, acc[i][2 * g][3] + b1),
                                 fmaxf(acc[i][2 * g + 1][2] + b2, acc[i][2 * g + 1][3] + b3));
                v0 = fmaxf(v0, __shfl_xor_sync(0xffffffffu, v0, 1));
                v0 = fmaxf(v0, __shfl_xor_sync(0xffffffffu, v0, 2));
                v1 = fmaxf(v1, __shfl_xor_sync(0xffffffffu, v1, 1));
                v1 = fmaxf(v1, __shfl_xor_sync(0xffffffffu, v1, 2));
                if ((lane & 3) == 0) {
                    int row = r0 + i * 16 + (lane >> 2);
                    m2[(size_t)row * HH + j0 + g] = v0;
                    m2[(size_t)(row + 8) * HH + j0 + g] = v1;
                }
            }
    }
}

// ---------------- m1 pool: P + q -> max16 -> m1f (fp32) + m13 (fp16 hi) ----
// blockIdx.y = head
__global__ void k_pool1() {
    if (g_done) return;
    int head = blockIdx.y;
    int idx = blockIdx.x * blockDim.x + threadIdx.x;
    int t = idx / HH;
    int j = idx - t * HH;
    if (t >= TN) return;
    const float* P = (head ? g_Pe : g_Ps) + (size_t)t * NP + j * 16;
    const float* q = g_q[head] + j * 16;
    float m = P[0] + q[0];
#pragma unroll
    for (int p = 1; p < PL; p++) m = fmaxf(m, P[p] + q[p]);
    g_m1f[head][(size_t)t * HH + j] = m;
    g_m13[head][(size_t)t * K3M + j] = __half_as_ushort(__float2half_rn(m));
}

// ---------------- small per-iteration kernels ----------------
__global__ void k_gates(const float* __restrict__ U, const float* __restrict__ Wih,
                        const float* __restrict__ Whh, const float* __restrict__ bih,
                        const float* __restrict__ bhh)
{
    if (g_done) return;
    int w = (blockIdx.x * blockDim.x + threadIdx.x) >> 5;
    int lane = threadIdx.x & 31;
    if (w >= 4 * HH) return;
    const float* Us = U + (size_t)g_start * UD;
    const float* Ue = U + (size_t)g_end * UD;
    const float* wr = Wih + (size_t)w * 800;
    const float* hr = Whh + (size_t)w * HH;
    float s = 0.f;
    for (int k = lane; k < UD; k += 32) s = fmaf(Us[k], wr[k], s);
    for (int k = lane; k < UD; k += 32) s = fmaf(Ue[k], wr[400 + k], s);
    for (int k = lane; k < HH; k += 32) s = fmaf(g_h[k], hr[k], s);
    for (int off = 16; off; off >>= 1) s += __shfl_xor_sync(0xffffffffu, s, off);
    if (lane == 0) g_gates[w] = s + bih[w] + bhh[w];
}

__device__ __forceinline__ float sigm(float x) { return 1.f / (1.f + expf(-x)); }

__global__ void k_lstm_update() {
    if (g_done) return;
    int j = threadIdx.x;
    if (j < HH) {
        float i = sigm(g_gates[j]);
        float f = sigm(g_gates[HH + j]);
        float g = tanhf(g_gates[2 * HH + j]);
        float o = sigm(g_gates[3 * HH + j]);
        float cc = f * g_c[j] + i * g;
        float hc = o * tanhf(cc);
        g_hc[j] = hc;
        g_h[j] = hc;
        g_c[j] = cc;
    }
}

__global__ void k_r(const float* __restrict__ U,
                    const float* __restrict__ w1s, const float* __restrict__ w1e)
{
    if (g_done) return;
    int w = (blockIdx.x * blockDim.x + threadIdx.x) >> 5;
    int lane = threadIdx.x & 31;
    if (w >= 2 * HH) return;
    int head = w / HH;
    int j = w - head * HH;
    const float* row = (head ? w1e : w1s) + (size_t)j * 1000;
    const float* Us = U + (size_t)g_start * UD;
    const float* Ue = U + (size_t)g_end * UD;
    float s = 0.f;
    for (int k = lane; k < HH; k += 32) s = fmaf(g_hc[k], row[k], s);
    for (int k = lane; k < UD; k += 32) s = fmaf(Us[k], row[200 + k], s);
    for (int k = lane; k < UD; k += 32) s = fmaf(Ue[k], row[600 + k], s);
    for (int off = 16; off; off >>= 1) s += __shfl_xor_sync(0xffffffffu, s, off);
    if (lane == 0) g_r[head][j] = tanhf(s);
}

// q'[head][j*16+p] = r[head] @ w2[p*200+j, 400:600] + b2[p*200+j]
__global__ void k_q(const float* __restrict__ w2s, const float* __restrict__ b2s,
                    const float* __restrict__ w2e, const float* __restrict__ b2e)
{
    if (g_done) return;
    int w = (blockIdx.x * blockDim.x + threadIdx.x) >> 5;
    int lane = threadIdx.x & 31;
    if (w >= 2 * NP) return;
    int head = w / NP;
    int n = w - head * NP;
    int j = n >> 4, p = n & 15;
    int src = p * 200 + j;
    const float* row = (head ? w2e : w2s) + (size_t)src * 600 + 400;
    const float* b2 = head ? b2e : b2s;
    const float* r = g_r[head];
    float s = 0.f;
    for (int k = lane; k < HH; k += 32) s = fmaf(r[k], row[k], s);
    for (int off = 16; off; off >>= 1) s += __shfl_xor_sync(0xffffffffu, s, off);
    if (lane == 0) g_q[head][n] = s + b2[src];
}

// blockIdx.y = head
__global__ void k_fc4(const float* __restrict__ w4s, const float* __restrict__ b4s,
                      const float* __restrict__ w4e, const float* __restrict__ b4e,
                      float* __restrict__ out, int it)
{
    int head = blockIdx.y;
    const float* w4 = head ? w4e : w4s;
    const float* b4 = head ? b4e : b4s;
    float* outRow = out + (size_t)(head * 4 + it) * TN;
    int t = (blockIdx.x * blockDim.x + threadIdx.x) >> 5;
    int lane = threadIdx.x & 31;
    if (t >= TN) return;
    if (it > 0 && g_done) {
        if (lane == 0) outRow[t] = (outRow - TN)[t];
        return;
    }
    const float* m1r = g_m1f[head] + (size_t)t * HH;
    const float* m2r = g_m2f[head] + (size_t)t * HH;
    float acc[PL];
#pragma unroll
    for (int p = 0; p < PL; p++) acc[p] = 0.f;
    for (int k = lane; k < HH; k += 32) {
        float v1 = m1r[k], v2 = m2r[k];
#pragma unroll
        for (int p = 0; p < PL; p++) {
            acc[p] = fmaf(v1, w4[p * 400 + k], acc[p]);
            acc[p] = fmaf(v2, w4[p * 400 + 200 + k], acc[p]);
        }
    }
#pragma unroll
    for (int p = 0; p < PL; p++)
        for (int off = 16; off; off >>= 1)
            acc[p] += __shfl_xor_sync(0xffffffffu, acc[p], off);
    if (lane == 0) {
        float best = acc[0] + b4[0];
#pragma unroll
        for (int p = 1; p < PL; p++) best = fmaxf(best, acc[p] + b4[p]);
        outRow[t] = best;
    }
}

__global__ void k_update(const float* __restrict__ arow, const float* __restrict__ brow,
                         int it)
{
    if (it > 0 && g_done) return;
    __shared__ float sv[256];
    __shared__ int si[256];
    __shared__ int res[2];
    int tid = threadIdx.x;
    for (int pass = 0; pass < 2; pass++) {
        const float* row = pass ? brow : arow;
        float bv = -3.4e38f; int bi = 0;
        for (int t = tid; t < TN; t += 256) {
            float v = row[t];
            if (v > bv) { bv = v; bi = t; }
        }
        sv[tid] = bv; si[tid] = bi;
        __syncthreads();
        for (int s = 128; s; s >>= 1) {
            if (tid < s) {
                float ov = sv[tid + s]; int oi = si[tid + s];
                if (ov > sv[tid] || (ov == sv[tid] && oi < si[tid])) {
                    sv[tid] = ov; si[tid] = oi;
                }
            }
            __syncthreads();
        }
        if (tid == 0) res[pass] = si[0];
        __syncthreads();
    }
    if (tid == 0) {
        int ns = res[0], ne = res[1];
        if (it == 0) {
            g_start = ns; g_end = ne; g_done = 0;
        } else {
            int nd = (ns == g_start && ne == g_end);
            g_start = ns; g_end = ne;
            g_done = nd;
        }
    }
}

// ---------------------------------------------------------------------------
extern "C" void kernel_launch(void* const* d_in, const int* in_sizes, int n_in,
                              void* d_out, int out_size)
{
    const float* U        = (const float*)d_in[0];
    const float* lstm_Wih = (const float*)d_in[1];
    const float* lstm_Whh = (const float*)d_in[2];
    const float* lstm_bih = (const float*)d_in[3];
    const float* lstm_bhh = (const float*)d_in[4];
    const float* s_fc1w = (const float*)d_in[5];
    const float* s_fc2w = (const float*)d_in[6];
    const float* s_fc2b = (const float*)d_in[7];
    const float* s_fc3w = (const float*)d_in[8];
    const float* s_fc3b = (const float*)d_in[9];
    const float* s_fc4w = (const float*)d_in[10];
    const float* s_fc4b = (const float*)d_in[11];
    const float* e_fc1w = (const float*)d_in[12];
    const float* e_fc2w = (const float*)d_in[13];
    const float* e_fc2b = (const float*)d_in[14];
    const float* e_fc3w = (const float*)d_in[15];
    const float* e_fc3b = (const float*)d_in[16];
    const float* e_fc4w = (const float*)d_in[17];
    const float* e_fc4b = (const float*)d_in[18];
    float* out = (float*)d_out;   // [alphas 4*T | betas 4*T]

    cudaFuncSetAttribute(k_mma, cudaFuncAttributeMaxDynamicSharedMemorySize, SMEM_BYTES);

    dim3 ggrid(NP / BN, TN / BM, 2);   // 25 x 128 x 2 heads

    k_init<<<1, 256>>>();
    k_convU3<<<(TN * K3U + 255) / 256, 256>>>(U);
    k_convB23<<<(NP * K3U + 255) / 256, 256>>>(s_fc2w, 0);
    k_convB23<<<(NP * K3U + 255) / 256, 256>>>(e_fc2w, 1);
    k_zero13<<<(TN * 112 + 255) / 256, 256>>>();
    k_mma<<<ggrid, 256, SMEM_BYTES>>>(0);
    k_convB33<<<(NP * K3M + 255) / 256, 256>>>(s_fc3w, s_fc3b, 0);
    k_convB33<<<(NP * K3M + 255) / 256, 256>>>(e_fc3w, e_fc3b, 1);

    dim3 pgrid((TN * HH + 255) / 256, 2);
    dim3 fgrid((TN * 32) / 256, 2);

    for (int it = 0; it < 4; it++) {
        k_gates<<<100, 256>>>(U, lstm_Wih, lstm_Whh, lstm_bih, lstm_bhh);
        k_lstm_update<<<1, 256>>>();
        k_r<<<50, 256>>>(U, s_fc1w, e_fc1w);
        k_q<<<800, 256>>>(s_fc2w, s_fc2b, e_fc2w, e_fc2b);
        k_pool1<<<pgrid, 256>>>();
        k_mma<<<ggrid, 256, SMEM_BYTES>>>(1);
        k_fc4<<<fgrid, 256>>>(s_fc4w, s_fc4b, e_fc4w, e_fc4b, out, it);
        k_update<<<1, 256>>>(out + (size_t)it * TN, out + (size_t)(4 + it) * TN, it);
    }
}

// round 14
// speedup vs baseline: 2.1780x; 1.3149x over previous
#include <cuda_runtime.h>
#include <cuda_bf16.h>
#include <cuda_fp16.h>
#include <math.h>
#include <stdint.h>

#define TN 16384
#define HH 200
#define PL 16
#define NP 3200
#define UD 400
#define K3U 448      // fp16 1-term: [0,400) Uhi*w2hi | pad 48
#define K3M 256      // fp16 1-term: [0,200) m1hi*w3hi | pad 56
#define BM 128
#define BN 128
#define BK 64
#define NSTG 3

// ---------------- static device scratch ----------------
__device__ __half g_Ps[(size_t)TN * NP];               // fp16 P (start head)
__device__ __half g_Pe[(size_t)TN * NP];               // fp16 P (end head)
__device__ unsigned short g_U3[(size_t)TN * K3U];      // fp16 [Uhi | 0]
__device__ unsigned short g_B23[2][(size_t)NP * K3U];  // fp16 [w2hi | 0], n permuted
__device__ unsigned short g_B33[2][(size_t)NP * K3M];  // fp16 [w3hi | 0], n permuted
__device__ unsigned short g_m13[2][(size_t)TN * K3M];  // fp16 [m1hi | 0]
__device__ float g_b3p[2][NP];
__device__ float g_m1f[2][(size_t)TN * HH];
__device__ float g_m2f[2][(size_t)TN * HH];
__device__ float g_h[HH], g_c[HH], g_hc[HH];
__device__ float g_gates[4 * HH];
__device__ float g_r[2][HH];
__device__ float g_q[2][NP];
__device__ int g_start, g_end, g_done;

// ---------------- ptx helpers ----------------
__device__ __forceinline__ uint32_t smem_u32(const void* p) {
    uint32_t a;
    asm("{ .reg .u64 t; cvta.to.shared.u64 t, %1; cvt.u32.u64 %0, t; }" : "=r"(a) : "l"(p));
    return a;
}
__device__ __forceinline__ void ldm_x4(uint32_t* r, uint32_t a) {
    asm volatile("ldmatrix.sync.aligned.m8n8.x4.shared.b16 {%0,%1,%2,%3}, [%4];"
                 : "=r"(r[0]), "=r"(r[1]), "=r"(r[2]), "=r"(r[3]) : "r"(a));
}
__device__ __forceinline__ void mma_fp(float* c, const uint32_t* a, const uint32_t* b) {
    asm volatile(
        "mma.sync.aligned.m16n8k16.row.col.f32.f16.f16.f32 "
        "{%0,%1,%2,%3}, {%4,%5,%6,%7}, {%8,%9}, {%0,%1,%2,%3};"
        : "+f"(c[0]), "+f"(c[1]), "+f"(c[2]), "+f"(c[3])
        : "r"(a[0]), "r"(a[1]), "r"(a[2]), "r"(a[3]), "r"(b[0]), "r"(b[1]));
}
__device__ __forceinline__ void cp16(uint32_t dst, const void* src) {
    asm volatile("cp.async.cg.shared.global [%0], [%1], 16;" :: "r"(dst), "l"(src));
}
__device__ __forceinline__ void cp_commit() {
    asm volatile("cp.async.commit_group;" ::: "memory");
}
__device__ __forceinline__ void cp_wait1() {
    asm volatile("cp.async.wait_group 1;" ::: "memory");
}

// ---------------- conversion kernels ----------------
// U fp16: [0,400) hi, pad [400,448)
__global__ void k_convU3(const float* __restrict__ U) {
    size_t idx = (size_t)blockIdx.x * blockDim.x + threadIdx.x;
    if (idx >= (size_t)TN * K3U) return;
    int k = (int)(idx % K3U);
    size_t t = idx / K3U;
    unsigned short o = 0;
    if (k < UD) o = __half_as_ushort(__float2half_rn(U[t * UD + k]));
    g_U3[idx] = o;
}
// fc2 weight fp16 (first 400 cols), n permuted: n=j*16+p <- p*200+j
__global__ void k_convB23(const float* __restrict__ w2, int head) {
    size_t idx = (size_t)blockIdx.x * blockDim.x + threadIdx.x;
    if (idx >= (size_t)NP * K3U) return;
    int k = (int)(idx % K3U);
    int n = (int)(idx / K3U);
    int j = n >> 4, p = n & 15;
    unsigned short o = 0;
    if (k < UD) o = __half_as_ushort(__float2half_rn(w2[(size_t)(p * 200 + j) * 600 + k]));
    g_B23[head][idx] = o;
}
// fc3 weight fp16, n permuted. [0,200) w3hi, [200,256) zero.
__global__ void k_convB33(const float* __restrict__ w3, const float* __restrict__ b3, int head) {
    size_t idx = (size_t)blockIdx.x * blockDim.x + threadIdx.x;
    if (idx >= (size_t)NP * K3M) return;
    int k = (int)(idx % K3M);
    int n = (int)(idx / K3M);
    int j = n >> 4, p = n & 15;
    int src = p * 200 + j;
    unsigned short o = 0;
    if (k < HH) o = __half_as_ushort(__float2half_rn(w3[(size_t)src * HH + k]));
    g_B33[head][idx] = o;
    if (k == 0) g_b3p[head][n] = b3[src];
}
__global__ void k_zero13() {   // zero m13 tails [200,256) once, both heads
    int idx = blockIdx.x * blockDim.x + threadIdx.x;
    int h = idx & 1;
    int r = idx >> 1;
    int t = r / 56, k = r - (r / 56) * 56;
    if (t < TN) g_m13[h][(size_t)t * K3M + 200 + k] = 0;
}
__global__ void k_init() {
    int j = threadIdx.x;
    if (j < HH) { g_h[j] = 0.f; g_c[j] = 0.f; }
    if (j == 0) { g_start = 0; g_end = 0; g_done = 0; }
}

// ---------------- HMMA GEMM (cp.async 3-stage, 32x64 warp tile, head=z) ----------
// mode 0: P[TN,NP] = U3 @ B23[head]^T -> fp16 g_Ps/g_Pe                 (NC=7)
// mode 1: fused fc3: maxpool16(m13 @ B33[head]^T + bias) -> g_m2f[head] (NC=4)
#define SMEM_STAGE 32768      // A 16KB + B 16KB
#define SMEM_BYTES (NSTG * SMEM_STAGE)

__global__ void __launch_bounds__(256) k_mma(int mode) {
    if (mode == 1 && g_done) return;
    extern __shared__ char smem[];
    __shared__ float s_bias[BN];
    const uint32_t sb = smem_u32(smem);
    const int tid = threadIdx.x;
    const int head = blockIdx.z;
    const int wid = tid >> 5, lane = tid & 31;
    const int wm = wid >> 1, wn = wid & 1;          // warp tile origin (4m x 2n)
    const int bm = blockIdx.y * BM, bn = blockIdx.x * BN;
    const int K3 = mode ? K3M : K3U;
    const int NC = K3 / BK;
    const unsigned short* A = mode ? g_m13[head] : g_U3;
    const unsigned short* B = mode ? g_B33[head] : g_B23[head];

    if (mode == 1 && tid < BN) s_bias[tid] = g_b3p[head][bn + tid];

    const int lrow = tid >> 1;          // 0..127
    const int lseg = tid & 1;           // 64B half of the 128B row
    const unsigned short* gA = A + (size_t)(bm + lrow) * K3 + lseg * 32;
    const unsigned short* gB = B + (size_t)(bn + lrow) * K3 + lseg * 32;

    uint32_t soff[4];
#pragma unroll
    for (int i = 0; i < 4; i++) {
        uint32_t off = (uint32_t)lrow * 128 + lseg * 64 + i * 16;
        soff[i] = off ^ ((off >> 3) & 0x70);
    }

#define ISSUE(c)                                                       \
    {                                                                  \
        const uint32_t st = sb + ((c) % NSTG) * SMEM_STAGE;            \
        const int k0 = (c) * BK;                                       \
        _Pragma("unroll")                                              \
        for (int i = 0; i < 4; i++) {                                  \
            cp16(st + soff[i], gA + k0 + i * 8);                       \
            cp16(st + 16384 + soff[i], gB + k0 + i * 8);               \
        }                                                              \
    }

    float acc[2][8][4];
#pragma unroll
    for (int i = 0; i < 2; i++)
#pragma unroll
        for (int j = 0; j < 8; j++)
#pragma unroll
            for (int q = 0; q < 4; q++) acc[i][j][q] = 0.f;

    ISSUE(0); cp_commit();
    ISSUE(1); cp_commit();

    for (int c = 0; c < NC; c++) {
        cp_wait1();
        __syncthreads();
        if (c + 2 < NC) ISSUE(c + 2);
        cp_commit();                         // empty group in tail keeps counting aligned

        const uint32_t base = sb + (c % NSTG) * SMEM_STAGE;
#pragma unroll
        for (int kk = 0; kk < 4; kk++) {
            uint32_t af[2][4];
#pragma unroll
            for (int i = 0; i < 2; i++) {
                uint32_t off = (uint32_t)(wm * 32 + i * 16 + (lane & 15)) * 128
                             + kk * 32 + ((lane >> 4) & 1) * 16;
                uint32_t sw = off ^ ((off >> 3) & 0x70);
                ldm_x4(af[i], base + sw);
            }
            uint32_t bf[4][4];
#pragma unroll
            for (int j = 0; j < 4; j++) {
                uint32_t nrow = wn * 64 + j * 16 + (lane & 7) + ((lane >> 4) & 1) * 8;
                uint32_t off = nrow * 128 + kk * 32 + ((lane >> 3) & 1) * 16;
                uint32_t sw = off ^ ((off >> 3) & 0x70);
                ldm_x4(bf[j], base + 16384 + sw);
            }
#pragma unroll
            for (int i = 0; i < 2; i++)
#pragma unroll
                for (int j = 0; j < 4; j++) {
                    mma_fp(acc[i][2 * j], af[i], &bf[j][0]);
                    mma_fp(acc[i][2 * j + 1], af[i], &bf[j][2]);
                }
        }
    }
#undef ISSUE

    // ---------------- epilogue ----------------
    if (mode == 0) {
        __half* C = head ? g_Pe : g_Ps;
        const int r0 = bm + wm * 32, n0 = bn + wn * 64;
#pragma unroll
        for (int i = 0; i < 2; i++)
#pragma unroll
            for (int jt = 0; jt < 8; jt++) {
                int row = r0 + i * 16 + (lane >> 2);
                int col = n0 + jt * 8 + (lane & 3) * 2;
                *(__half2*)(C + (size_t)row * NP + col) =
                    __floats2half2_rn(acc[i][jt][0], acc[i][jt][1]);
                *(__half2*)(C + (size_t)(row + 8) * NP + col) =
                    __floats2half2_rn(acc[i][jt][2], acc[i][jt][3]);
            }
    } else {
        const int r0 = bm + wm * 32;
        const int j0 = (bn >> 4) + wn * 4;
        float* m2 = g_m2f[head];
#pragma unroll
        for (int i = 0; i < 2; i++)
#pragma unroll
            for (int g = 0; g < 4; g++) {
                int nb = wn * 64 + g * 16 + (lane & 3) * 2;
                float b0 = s_bias[nb], b1 = s_bias[nb + 1];
                float b2 = s_bias[nb + 8], b3 = s_bias[nb + 9];
                float v0 = fmaxf(fmaxf(acc[i][2 * g][0] + b0, acc[i][2 * g][1] + b1),
                                 fmaxf(acc[i][2 * g + 1][0] + b2, acc[i][2 * g + 1][1] + b3));
                float v1 = fmaxf(fmaxf(acc[i][2 * g][2] + b0, acc[i][2 * g][3] + b1),
                                 fmaxf(acc[i][2 * g + 1][2] + b2, acc[i][2 * g + 1][3] + b3));
                v0 = fmaxf(v0, __shfl_xor_sync(0xffffffffu, v0, 1));
                v0 = fmaxf(v0, __shfl_xor_sync(0xffffffffu, v0, 2));
                v1 = fmaxf(v1, __shfl_xor_sync(0xffffffffu, v1, 1));
                v1 = fmaxf(v1, __shfl_xor_sync(0xffffffffu, v1, 2));
                if ((lane & 3) == 0) {
                    int row = r0 + i * 16 + (lane >> 2);
                    m2[(size_t)row * HH + j0 + g] = v0;
                    m2[(size_t)(row + 8) * HH + j0 + g] = v1;
                }
            }
    }
}

// ---------------- m1 pool: P(fp16) + q -> max16 -> m1f (fp32) + m13 (fp16) ----
// blockIdx.y = head
__global__ void k_pool1() {
    if (g_done) return;
    int head = blockIdx.y;
    int idx = blockIdx.x * blockDim.x + threadIdx.x;
    int t = idx / HH;
    int j = idx - t * HH;
    if (t >= TN) return;
    const __half2* P2 = (const __half2*)((head ? g_Pe : g_Ps) + (size_t)t * NP + j * 16);
    const float* q = g_q[head] + j * 16;
    float m = -3.4e38f;
#pragma unroll
    for (int p = 0; p < 8; p++) {
        float2 v = __half22float2(P2[p]);
        m = fmaxf(m, v.x + q[2 * p]);
        m = fmaxf(m, v.y + q[2 * p + 1]);
    }
    g_m1f[head][(size_t)t * HH + j] = m;
    g_m13[head][(size_t)t * K3M + j] = __half_as_ushort(__float2half_rn(m));
}

// ---------------- small per-iteration kernels ----------------
__global__ void k_gates(const float* __restrict__ U, const float* __restrict__ Wih,
                        const float* __restrict__ Whh, const float* __restrict__ bih,
                        const float* __restrict__ bhh)
{
    if (g_done) return;
    int w = (blockIdx.x * blockDim.x + threadIdx.x) >> 5;
    int lane = threadIdx.x & 31;
    if (w >= 4 * HH) return;
    const float* Us = U + (size_t)g_start * UD;
    const float* Ue = U + (size_t)g_end * UD;
    const float* wr = Wih + (size_t)w * 800;
    const float* hr = Whh + (size_t)w * HH;
    float s = 0.f;
    for (int k = lane; k < UD; k += 32) s = fmaf(Us[k], wr[k], s);
    for (int k = lane; k < UD; k += 32) s = fmaf(Ue[k], wr[400 + k], s);
    for (int k = lane; k < HH; k += 32) s = fmaf(g_h[k], hr[k], s);
    for (int off = 16; off; off >>= 1) s += __shfl_xor_sync(0xffffffffu, s, off);
    if (lane == 0) g_gates[w] = s + bih[w] + bhh[w];
}

__device__ __forceinline__ float sigm(float x) { return 1.f / (1.f + expf(-x)); }

__global__ void k_lstm_update() {
    if (g_done) return;
    int j = threadIdx.x;
    if (j < HH) {
        float i = sigm(g_gates[j]);
        float f = sigm(g_gates[HH + j]);
        float g = tanhf(g_gates[2 * HH + j]);
        float o = sigm(g_gates[3 * HH + j]);
        float cc = f * g_c[j] + i * g;
        float hc = o * tanhf(cc);
        g_hc[j] = hc;
        g_h[j] = hc;
        g_c[j] = cc;
    }
}

__global__ void k_r(const float* __restrict__ U,
                    const float* __restrict__ w1s, const float* __restrict__ w1e)
{
    if (g_done) return;
    int w = (blockIdx.x * blockDim.x + threadIdx.x) >> 5;
    int lane = threadIdx.x & 31;
    if (w >= 2 * HH) return;
    int head = w / HH;
    int j = w - head * HH;
    const float* row = (head ? w1e : w1s) + (size_t)j * 1000;
    const float* Us = U + (size_t)g_start * UD;
    const float* Ue = U + (size_t)g_end * UD;
    float s = 0.f;
    for (int k = lane; k < HH; k += 32) s = fmaf(g_hc[k], row[k], s);
    for (int k = lane; k < UD; k += 32) s = fmaf(Us[k], row[200 + k], s);
    for (int k = lane; k < UD; k += 32) s = fmaf(Ue[k], row[600 + k], s);
    for (int off = 16; off; off >>= 1) s += __shfl_xor_sync(0xffffffffu, s, off);
    if (lane == 0) g_r[head][j] = tanhf(s);
}

// q'[head][j*16+p] = r[head] @ w2[p*200+j, 400:600] + b2[p*200+j]
__global__ void k_q(const float* __restrict__ w2s, const float* __restrict__ b2s,
                    const float* __restrict__ w2e, const float* __restrict__ b2e)
{
    if (g_done) return;
    int w = (blockIdx.x * blockDim.x + threadIdx.x) >> 5;
    int lane = threadIdx.x & 31;
    if (w >= 2 * NP) return;
    int head = w / NP;
    int n = w - head * NP;
    int j = n >> 4, p = n & 15;
    int src = p * 200 + j;
    const float* row = (head ? w2e : w2s) + (size_t)src * 600 + 400;
    const float* b2 = head ? b2e : b2s;
    const float* r = g_r[head];
    float s = 0.f;
    for (int k = lane; k < HH; k += 32) s = fmaf(r[k], row[k], s);
    for (int off = 16; off; off >>= 1) s += __shfl_xor_sync(0xffffffffu, s, off);
    if (lane == 0) g_q[head][n] = s + b2[src];
}

// blockIdx.y = head
__global__ void k_fc4(const float* __restrict__ w4s, const float* __restrict__ b4s,
                      const float* __restrict__ w4e, const float* __restrict__ b4e,
                      float* __restrict__ out, int it)
{
    int head = blockIdx.y;
    const float* w4 = head ? w4e : w4s;
    const float* b4 = head ? b4e : b4s;
    float* outRow = out + (size_t)(head * 4 + it) * TN;
    int t = (blockIdx.x * blockDim.x + threadIdx.x) >> 5;
    int lane = threadIdx.x & 31;
    if (t >= TN) return;
    if (it > 0 && g_done) {
        if (lane == 0) outRow[t] = (outRow - TN)[t];
        return;
    }
    const float* m1r = g_m1f[head] + (size_t)t * HH;
    const float* m2r = g_m2f[head] + (size_t)t * HH;
    float acc[PL];
#pragma unroll
    for (int p = 0; p < PL; p++) acc[p] = 0.f;
    for (int k = lane; k < HH; k += 32) {
        float v1 = m1r[k], v2 = m2r[k];
#pragma unroll
        for (int p = 0; p < PL; p++) {
            acc[p] = fmaf(v1, w4[p * 400 + k], acc[p]);
            acc[p] = fmaf(v2, w4[p * 400 + 200 + k], acc[p]);
        }
    }
#pragma unroll
    for (int p = 0; p < PL; p++)
        for (int off = 16; off; off >>= 1)
            acc[p] += __shfl_xor_sync(0xffffffffu, acc[p], off);
    if (lane == 0) {
        float best = acc[0] + b4[0];
#pragma unroll
        for (int p = 1; p < PL; p++) best = fmaxf(best, acc[p] + b4[p]);
        outRow[t] = best;
    }
}

__global__ void k_update(const float* __restrict__ arow, const float* __restrict__ brow,
                         int it)
{
    if (it > 0 && g_done) return;
    __shared__ float sv[256];
    __shared__ int si[256];
    __shared__ int res[2];
    int tid = threadIdx.x;
    for (int pass = 0; pass < 2; pass++) {
        const float* row = pass ? brow : arow;
        float bv = -3.4e38f; int bi = 0;
        for (int t = tid; t < TN; t += 256) {
            float v = row[t];
            if (v > bv) { bv = v; bi = t; }
        }
        sv[tid] = bv; si[tid] = bi;
        __syncthreads();
        for (int s = 128; s; s >>= 1) {
            if (tid < s) {
                float ov = sv[tid + s]; int oi = si[tid + s];
                if (ov > sv[tid] || (ov == sv[tid] && oi < si[tid])) {
                    sv[tid] = ov; si[tid] = oi;
                }
            }
            __syncthreads();
        }
        if (tid == 0) res[pass] = si[0];
        __syncthreads();
    }
    if (tid == 0) {
        int ns = res[0], ne = res[1];
        if (it == 0) {
            g_start = ns; g_end = ne; g_done = 0;
        } else {
            int nd = (ns == g_start && ne == g_end);
            g_start = ns; g_end = ne;
            g_done = nd;
        }
    }
}

// ---------------------------------------------------------------------------
extern "C" void kernel_launch(void* const* d_in, const int* in_sizes, int n_in,
                              void* d_out, int out_size)
{
    const float* U        = (const float*)d_in[0];
    const float* lstm_Wih = (const float*)d_in[1];
    const float* lstm_Whh = (const float*)d_in[2];
    const float* lstm_bih = (const float*)d_in[3];
    const float* lstm_bhh = (const float*)d_in[4];
    const float* s_fc1w = (const float*)d_in[5];
    const float* s_fc2w = (const float*)d_in[6];
    const float* s_fc2b = (const float*)d_in[7];
    const float* s_fc3w = (const float*)d_in[8];
    const float* s_fc3b = (const float*)d_in[9];
    const float* s_fc4w = (const float*)d_in[10];
    const float* s_fc4b = (const float*)d_in[11];
    const float* e_fc1w = (const float*)d_in[12];
    const float* e_fc2w = (const float*)d_in[13];
    const float* e_fc2b = (const float*)d_in[14];
    const float* e_fc3w = (const float*)d_in[15];
    const float* e_fc3b = (const float*)d_in[16];
    const float* e_fc4w = (const float*)d_in[17];
    const float* e_fc4b = (const float*)d_in[18];
    float* out = (float*)d_out;   // [alphas 4*T | betas 4*T]

    cudaFuncSetAttribute(k_mma, cudaFuncAttributeMaxDynamicSharedMemorySize, SMEM_BYTES);

    dim3 ggrid(NP / BN, TN / BM, 2);   // 25 x 128 x 2 heads

    k_init<<<1, 256>>>();
    k_convU3<<<(TN * K3U + 255) / 256, 256>>>(U);
    k_convB23<<<(NP * K3U + 255) / 256, 256>>>(s_fc2w, 0);
    k_convB23<<<(NP * K3U + 255) / 256, 256>>>(e_fc2w, 1);
    k_zero13<<<(TN * 112 + 255) / 256, 256>>>();
    k_mma<<<ggrid, 256, SMEM_BYTES>>>(0);
    k_convB33<<<(NP * K3M + 255) / 256, 256>>>(s_fc3w, s_fc3b, 0);
    k_convB33<<<(NP * K3M + 255) / 256, 256>>>(e_fc3w, e_fc3b, 1);

    dim3 pgrid((TN * HH + 255) / 256, 2);
    dim3 fgrid((TN * 32) / 256, 2);

    for (int it = 0; it < 4; it++) {
        k_gates<<<100, 256>>>(U, lstm_Wih, lstm_Whh, lstm_bih, lstm_bhh);
        k_lstm_update<<<1, 256>>>();
        k_r<<<50, 256>>>(U, s_fc1w, e_fc1w);
        k_q<<<800, 256>>>(s_fc2w, s_fc2b, e_fc2w, e_fc2b);
        k_pool1<<<pgrid, 256>>>();
        k_mma<<<ggrid, 256, SMEM_BYTES>>>(1);
        k_fc4<<<fgrid, 256>>>(s_fc4w, s_fc4b, e_fc4w, e_fc4b, out, it);
        k_update<<<1, 256>>>(out + (size_t)it * TN, out + (size_t)(4 + it) * TN, it);
    }
}

// round 17
// speedup vs baseline: 2.8296x; 1.2991x over previous
#include <cuda_runtime.h>
#include <cuda_bf16.h>
#include <cuda_fp16.h>
#include <math.h>
#include <stdint.h>

#define TN 16384
#define HH 200
#define PL 16
#define NP 3200
#define UD 400
#define K3U 448      // fp16 1-term: [0,400) Uhi*w2hi | pad 48
#define K3M 256      // fp16 1-term: [0,200) m1hi*w3hi | pad 56
#define BM 128
#define BN 128
#define BK 64
#define NSTG 3

// ---------------- static device scratch ----------------
__device__ __half g_Ps[(size_t)TN * NP];               // fp16 P (start head)
__device__ __half g_Pe[(size_t)TN * NP];               // fp16 P (end head)
__device__ unsigned short g_U3[(size_t)TN * K3U];      // fp16 [Uhi | 0]
__device__ unsigned short g_B23[2][(size_t)NP * K3U];  // fp16 [w2hi | 0], n permuted
__device__ unsigned short g_B33[2][(size_t)NP * K3M];  // fp16 [w3hi | 0], n permuted
__device__ unsigned short g_m13[2][(size_t)TN * K3M];  // fp16 m1 (stride 256, pad 0)
__device__ __half g_m23[2][(size_t)TN * HH];           // fp16 m2 (stride 200)
__device__ float g_b3p[2][NP];
__device__ float g_h[HH], g_c[HH], g_hc[HH];
__device__ float g_gates[4 * HH];
__device__ float g_r[2][HH];
__device__ float g_q[2][NP];
__device__ int g_start, g_end, g_done;

// ---------------- ptx helpers ----------------
__device__ __forceinline__ uint32_t smem_u32(const void* p) {
    uint32_t a;
    asm("{ .reg .u64 t; cvta.to.shared.u64 t, %1; cvt.u32.u64 %0, t; }" : "=r"(a) : "l"(p));
    return a;
}
__device__ __forceinline__ void ldm_x4(uint32_t* r, uint32_t a) {
    asm volatile("ldmatrix.sync.aligned.m8n8.x4.shared.b16 {%0,%1,%2,%3}, [%4];"
                 : "=r"(r[0]), "=r"(r[1]), "=r"(r[2]), "=r"(r[3]) : "r"(a));
}
__device__ __forceinline__ void mma_fp(float* c, const uint32_t* a, const uint32_t* b) {
    asm volatile(
        "mma.sync.aligned.m16n8k16.row.col.f32.f16.f16.f32 "
        "{%0,%1,%2,%3}, {%4,%5,%6,%7}, {%8,%9}, {%0,%1,%2,%3};"
        : "+f"(c[0]), "+f"(c[1]), "+f"(c[2]), "+f"(c[3])
        : "r"(a[0]), "r"(a[1]), "r"(a[2]), "r"(a[3]), "r"(b[0]), "r"(b[1]));
}
__device__ __forceinline__ void cp16(uint32_t dst, const void* src) {
    asm volatile("cp.async.cg.shared.global [%0], [%1], 16;" :: "r"(dst), "l"(src));
}
__device__ __forceinline__ void cp_commit() {
    asm volatile("cp.async.commit_group;" ::: "memory");
}
__device__ __forceinline__ void cp_wait1() {
    asm volatile("cp.async.wait_group 1;" ::: "memory");
}

// ---------------- conversion kernels ----------------
// U fp16: [0,400) hi, pad [400,448)
__global__ void k_convU3(const float* __restrict__ U) {
    size_t idx = (size_t)blockIdx.x * blockDim.x + threadIdx.x;
    if (idx >= (size_t)TN * K3U) return;
    int k = (int)(idx % K3U);
    size_t t = idx / K3U;
    unsigned short o = 0;
    if (k < UD) o = __half_as_ushort(__float2half_rn(U[t * UD + k]));
    g_U3[idx] = o;
}
// fc2 weight fp16 (first 400 cols), n permuted: n=j*16+p <- p*200+j
__global__ void k_convB23(const float* __restrict__ w2, int head) {
    size_t idx = (size_t)blockIdx.x * blockDim.x + threadIdx.x;
    if (idx >= (size_t)NP * K3U) return;
    int k = (int)(idx % K3U);
    int n = (int)(idx / K3U);
    int j = n >> 4, p = n & 15;
    unsigned short o = 0;
    if (k < UD) o = __half_as_ushort(__float2half_rn(w2[(size_t)(p * 200 + j) * 600 + k]));
    g_B23[head][idx] = o;
}
// fc3 weight fp16, n permuted. [0,200) w3hi, [200,256) zero.
__global__ void k_convB33(const float* __restrict__ w3, const float* __restrict__ b3, int head) {
    size_t idx = (size_t)blockIdx.x * blockDim.x + threadIdx.x;
    if (idx >= (size_t)NP * K3M) return;
    int k = (int)(idx % K3M);
    int n = (int)(idx / K3M);
    int j = n >> 4, p = n & 15;
    int src = p * 200 + j;
    unsigned short o = 0;
    if (k < HH) o = __half_as_ushort(__float2half_rn(w3[(size_t)src * HH + k]));
    g_B33[head][idx] = o;
    if (k == 0) g_b3p[head][n] = b3[src];
}
__global__ void k_zero13() {   // zero m13 tails [200,256) once, both heads
    int idx = blockIdx.x * blockDim.x + threadIdx.x;
    int h = idx & 1;
    int r = idx >> 1;
    int t = r / 56, k = r - (r / 56) * 56;
    if (t < TN) g_m13[h][(size_t)t * K3M + 200 + k] = 0;
}
__global__ void k_init() {
    int j = threadIdx.x;
    if (j < HH) { g_h[j] = 0.f; g_c[j] = 0.f; }
    if (j == 0) { g_start = 0; g_end = 0; g_done = 0; }
}

// ---------------- HMMA GEMM (cp.async 3-stage, 32x64 warp tile, head=z) ----------
// mode 0: P[TN,NP] = U3 @ B23[head]^T -> fp16 g_Ps/g_Pe                 (NC=7)
// mode 1: fused fc3: maxpool16(m13 @ B33[head]^T + bias) -> g_m23[head] (NC=4)
#define SMEM_STAGE 32768      // A 16KB + B 16KB
#define SMEM_BYTES (NSTG * SMEM_STAGE)

__global__ void __launch_bounds__(256) k_mma(int mode) {
    if (mode == 1 && g_done) return;
    extern __shared__ char smem[];
    __shared__ float s_bias[BN];
    const uint32_t sb = smem_u32(smem);
    const int tid = threadIdx.x;
    const int head = blockIdx.z;
    const int wid = tid >> 5, lane = tid & 31;
    const int wm = wid >> 1, wn = wid & 1;          // warp tile origin (4m x 2n)
    const int bm = blockIdx.y * BM, bn = blockIdx.x * BN;
    const int K3 = mode ? K3M : K3U;
    const int NC = K3 / BK;
    const unsigned short* A = mode ? g_m13[head] : g_U3;
    const unsigned short* B = mode ? g_B33[head] : g_B23[head];

    if (mode == 1 && tid < BN) s_bias[tid] = g_b3p[head][bn + tid];

    const int lrow = tid >> 1;          // 0..127
    const int lseg = tid & 1;           // 64B half of the 128B row
    const unsigned short* gA = A + (size_t)(bm + lrow) * K3 + lseg * 32;
    const unsigned short* gB = B + (size_t)(bn + lrow) * K3 + lseg * 32;

    uint32_t soff[4];
#pragma unroll
    for (int i = 0; i < 4; i++) {
        uint32_t off = (uint32_t)lrow * 128 + lseg * 64 + i * 16;
        soff[i] = off ^ ((off >> 3) & 0x70);
    }

#define ISSUE(c)                                                       \
    {                                                                  \
        const uint32_t st = sb + ((c) % NSTG) * SMEM_STAGE;            \
        const int k0 = (c) * BK;                                       \
        _Pragma("unroll")                                              \
        for (int i = 0; i < 4; i++) {                                  \
            cp16(st + soff[i], gA + k0 + i * 8);                       \
            cp16(st + 16384 + soff[i], gB + k0 + i * 8);               \
        }                                                              \
    }

    float acc[2][8][4];
#pragma unroll
    for (int i = 0; i < 2; i++)
#pragma unroll
        for (int j = 0; j < 8; j++)
#pragma unroll
            for (int q = 0; q < 4; q++) acc[i][j][q] = 0.f;

    ISSUE(0); cp_commit();
    ISSUE(1); cp_commit();

    for (int c = 0; c < NC; c++) {
        cp_wait1();
        __syncthreads();
        if (c + 2 < NC) ISSUE(c + 2);
        cp_commit();                         // empty group in tail keeps counting aligned

        const uint32_t base = sb + (c % NSTG) * SMEM_STAGE;
#pragma unroll
        for (int kk = 0; kk < 4; kk++) {
            uint32_t af[2][4];
#pragma unroll
            for (int i = 0; i < 2; i++) {
                uint32_t off = (uint32_t)(wm * 32 + i * 16 + (lane & 15)) * 128
                             + kk * 32 + ((lane >> 4) & 1) * 16;
                uint32_t sw = off ^ ((off >> 3) & 0x70);
                ldm_x4(af[i], base + sw);
            }
            uint32_t bf[4][4];
#pragma unroll
            for (int j = 0; j < 4; j++) {
                uint32_t nrow = wn * 64 + j * 16 + (lane & 7) + ((lane >> 4) & 1) * 8;
                uint32_t off = nrow * 128 + kk * 32 + ((lane >> 3) & 1) * 16;
                uint32_t sw = off ^ ((off >> 3) & 0x70);
                ldm_x4(bf[j], base + 16384 + sw);
            }
#pragma unroll
            for (int i = 0; i < 2; i++)
#pragma unroll
                for (int j = 0; j < 4; j++) {
                    mma_fp(acc[i][2 * j], af[i], &bf[j][0]);
                    mma_fp(acc[i][2 * j + 1], af[i], &bf[j][2]);
                }
        }
    }
#undef ISSUE

    // ---------------- epilogue ----------------
    if (mode == 0) {
        __half* C = head ? g_Pe : g_Ps;
        const int r0 = bm + wm * 32, n0 = bn + wn * 64;
#pragma unroll
        for (int i = 0; i < 2; i++)
#pragma unroll
            for (int jt = 0; jt < 8; jt++) {
                int row = r0 + i * 16 + (lane >> 2);
                int col = n0 + jt * 8 + (lane & 3) * 2;
                *(__half2*)(C + (size_t)row * NP + col) =
                    __floats2half2_rn(acc[i][jt][0], acc[i][jt][1]);
                *(__half2*)(C + (size_t)(row + 8) * NP + col) =
                    __floats2half2_rn(acc[i][jt][2], acc[i][jt][3]);
            }
    } else {
        const int r0 = bm + wm * 32;
        const int j0 = (bn >> 4) + wn * 4;
        __half* m2 = g_m23[head];
#pragma unroll
        for (int i = 0; i < 2; i++)
#pragma unroll
            for (int g = 0; g < 4; g++) {
                int nb = wn * 64 + g * 16 + (lane & 3) * 2;
                float b0 = s_bias[nb], b1 = s_bias[nb + 1];
                float b2 = s_bias[nb + 8], b3 = s_bias[nb + 9];
                float v0 = fmaxf(fmaxf(acc[i][2 * g][0] + b0, acc[i][2 * g][1] + b1),
                                 fmaxf(acc[i][2 * g + 1][0] + b2, acc[i][2 * g + 1][1] + b3));
                float v1 = fmaxf(fmaxf(acc[i][2 * g][2] + b0, acc[i][2 * g][3] + b1),
                                 fmaxf(acc[i][2 * g + 1][2] + b2, acc[i][2 * g + 1][3] + b3));
                v0 = fmaxf(v0, __shfl_xor_sync(0xffffffffu, v0, 1));
                v0 = fmaxf(v0, __shfl_xor_sync(0xffffffffu, v0, 2));
                v1 = fmaxf(v1, __shfl_xor_sync(0xffffffffu, v1, 1));
                v1 = fmaxf(v1, __shfl_xor_sync(0xffffffffu, v1, 2));
                if ((lane & 3) == 0) {
                    int row = r0 + i * 16 + (lane >> 2);
                    m2[(size_t)row * HH + j0 + g] = __float2half_rn(v0);
                    m2[(size_t)(row + 8) * HH + j0 + g] = __float2half_rn(v1);
                }
            }
    }
}

// ---------------- m1 pool: P(fp16) + q -> max16 -> m13 (fp16) ----
// blockIdx.y = head
__global__ void k_pool1() {
    if (g_done) return;
    int head = blockIdx.y;
    int idx = blockIdx.x * blockDim.x + threadIdx.x;
    int t = idx / HH;
    int j = idx - t * HH;
    if (t >= TN) return;
    const uint4* P4 = (const uint4*)((head ? g_Pe : g_Ps) + (size_t)t * NP + j * 16);
    const float4* q4 = (const float4*)(g_q[head] + j * 16);
    uint4 pa = P4[0], pb = P4[1];
    float4 qa = q4[0], qb = q4[1], qc = q4[2], qd = q4[3];
    uint32_t pw[8] = {pa.x, pa.y, pa.z, pa.w, pb.x, pb.y, pb.z, pb.w};
    float qv[16] = {qa.x, qa.y, qa.z, qa.w, qb.x, qb.y, qb.z, qb.w,
                    qc.x, qc.y, qc.z, qc.w, qd.x, qd.y, qd.z, qd.w};
    float m = -3.4e38f;
#pragma unroll
    for (int p = 0; p < 8; p++) {
        float2 v = __half22float2(*(const __half2*)&pw[p]);
        m = fmaxf(m, v.x + qv[2 * p]);
        m = fmaxf(m, v.y + qv[2 * p + 1]);
    }
    g_m13[head][(size_t)t * K3M + j] = __half_as_ushort(__float2half_rn(m));
}

// ---------------- small per-iteration kernels ----------------
__global__ void k_gates(const float* __restrict__ U, const float* __restrict__ Wih,
                        const float* __restrict__ Whh, const float* __restrict__ bih,
                        const float* __restrict__ bhh)
{
    if (g_done) return;
    int w = (blockIdx.x * blockDim.x + threadIdx.x) >> 5;
    int lane = threadIdx.x & 31;
    if (w >= 4 * HH) return;
    const float* Us = U + (size_t)g_start * UD;
    const float* Ue = U + (size_t)g_end * UD;
    const float* wr = Wih + (size_t)w * 800;
    const float* hr = Whh + (size_t)w * HH;
    float s = 0.f;
    for (int k = lane; k < UD; k += 32) s = fmaf(Us[k], wr[k], s);
    for (int k = lane; k < UD; k += 32) s = fmaf(Ue[k], wr[400 + k], s);
    for (int k = lane; k < HH; k += 32) s = fmaf(g_h[k], hr[k], s);
    for (int off = 16; off; off >>= 1) s += __shfl_xor_sync(0xffffffffu, s, off);
    if (lane == 0) g_gates[w] = s + bih[w] + bhh[w];
}

__device__ __forceinline__ float sigm(float x) { return 1.f / (1.f + expf(-x)); }

__global__ void k_lstm_update() {
    if (g_done) return;
    int j = threadIdx.x;
    if (j < HH) {
        float i = sigm(g_gates[j]);
        float f = sigm(g_gates[HH + j]);
        float g = tanhf(g_gates[2 * HH + j]);
        float o = sigm(g_gates[3 * HH + j]);
        float cc = f * g_c[j] + i * g;
        float hc = o * tanhf(cc);
        g_hc[j] = hc;
        g_h[j] = hc;
        g_c[j] = cc;
    }
}

__global__ void k_r(const float* __restrict__ U,
                    const float* __restrict__ w1s, const float* __restrict__ w1e)
{
    if (g_done) return;
    int w = (blockIdx.x * blockDim.x + threadIdx.x) >> 5;
    int lane = threadIdx.x & 31;
    if (w >= 2 * HH) return;
    int head = w / HH;
    int j = w - head * HH;
    const float* row = (head ? w1e : w1s) + (size_t)j * 1000;
    const float* Us = U + (size_t)g_start * UD;
    const float* Ue = U + (size_t)g_end * UD;
    float s = 0.f;
    for (int k = lane; k < HH; k += 32) s = fmaf(g_hc[k], row[k], s);
    for (int k = lane; k < UD; k += 32) s = fmaf(Us[k], row[200 + k], s);
    for (int k = lane; k < UD; k += 32) s = fmaf(Ue[k], row[600 + k], s);
    for (int off = 16; off; off >>= 1) s += __shfl_xor_sync(0xffffffffu, s, off);
    if (lane == 0) g_r[head][j] = tanhf(s);
}

// q'[head][j*16+p] = r[head] @ w2[p*200+j, 400:600] + b2[p*200+j]
__global__ void k_q(const float* __restrict__ w2s, const float* __restrict__ b2s,
                    const float* __restrict__ w2e, const float* __restrict__ b2e)
{
    if (g_done) return;
    int w = (blockIdx.x * blockDim.x + threadIdx.x) >> 5;
    int lane = threadIdx.x & 31;
    if (w >= 2 * NP) return;
    int head = w / NP;
    int n = w - head * NP;
    int j = n >> 4, p = n & 15;
    int src = p * 200 + j;
    const float* row = (head ? w2e : w2s) + (size_t)src * 600 + 400;
    const float* b2 = head ? b2e : b2s;
    const float* r = g_r[head];
    float s = 0.f;
    for (int k = lane; k < HH; k += 32) s = fmaf(r[k], row[k], s);
    for (int off = 16; off; off >>= 1) s += __shfl_xor_sync(0xffffffffu, s, off);
    if (lane == 0) g_q[head][n] = s + b2[src];
}

// blockIdx.y = head. m1/m2 read as fp16 half2 pairs.
__global__ void k_fc4(const float* __restrict__ w4s, const float* __restrict__ b4s,
                      const float* __restrict__ w4e, const float* __restrict__ b4e,
                      float* __restrict__ out, int it)
{
    int head = blockIdx.y;
    const float* w4 = head ? w4e : w4s;
    const float* b4 = head ? b4e : b4s;
    float* outRow = out + (size_t)(head * 4 + it) * TN;
    int t = (blockIdx.x * blockDim.x + threadIdx.x) >> 5;
    int lane = threadIdx.x & 31;
    if (t >= TN) return;
    if (it > 0 && g_done) {
        if (lane == 0) outRow[t] = (outRow - TN)[t];
        return;
    }
    const __half2* m1h = (const __half2*)(g_m13[head] + (size_t)t * K3M);
    const __half2* m2h = (const __half2*)(g_m23[head] + (size_t)t * HH);
    float acc[PL];
#pragma unroll
    for (int p = 0; p < PL; p++) acc[p] = 0.f;
#pragma unroll
    for (int i = 0; i < 3; i++) {
        int k0 = 2 * lane + 64 * i;
        float2 v1 = __half22float2(m1h[k0 >> 1]);
        float2 v2 = __half22float2(m2h[k0 >> 1]);
#pragma unroll
        for (int p = 0; p < PL; p++) {
            acc[p] = fmaf(v1.x, w4[p * 400 + k0], acc[p]);
            acc[p] = fmaf(v1.y, w4[p * 400 + k0 + 1], acc[p]);
            acc[p] = fmaf(v2.x, w4[p * 400 + 200 + k0], acc[p]);
            acc[p] = fmaf(v2.y, w4[p * 400 + 200 + k0 + 1], acc[p]);
        }
    }
    if (lane < 4) {
        int k0 = 192 + 2 * lane;
        float2 v1 = __half22float2(m1h[k0 >> 1]);
        float2 v2 = __half22float2(m2h[k0 >> 1]);
#pragma unroll
        for (int p = 0; p < PL; p++) {
            acc[p] = fmaf(v1.x, w4[p * 400 + k0], acc[p]);
            acc[p] = fmaf(v1.y, w4[p * 400 + k0 + 1], acc[p]);
            acc[p] = fmaf(v2.x, w4[p * 400 + 200 + k0], acc[p]);
            acc[p] = fmaf(v2.y, w4[p * 400 + 200 + k0 + 1], acc[p]);
        }
    }
#pragma unroll
    for (int p = 0; p < PL; p++)
        for (int off = 16; off; off >>= 1)
            acc[p] += __shfl_xor_sync(0xffffffffu, acc[p], off);
    if (lane == 0) {
        float best = acc[0] + b4[0];
#pragma unroll
        for (int p = 1; p < PL; p++) best = fmaxf(best, acc[p] + b4[p]);
        outRow[t] = best;
    }
}

// 512 threads: alpha/beta argmax passes run in parallel (tid>>8 = pass)
__global__ void k_update(const float* __restrict__ arow, const float* __restrict__ brow,
                         int it)
{
    if (it > 0 && g_done) return;
    __shared__ float sv[512];
    __shared__ int si[512];
    int tid = threadIdx.x;
    int pass = tid >> 8, tl = tid & 255;
    const float* row = pass ? brow : arow;
    float bv = -3.4e38f; int bi = 0;
    for (int t = tl; t < TN; t += 256) {
        float v = row[t];
        if (v > bv) { bv = v; bi = t; }
    }
    sv[tid] = bv; si[tid] = bi;
    __syncthreads();
    for (int s = 128; s; s >>= 1) {
        if (tl < s) {
            float ov = sv[tid + s]; int oi = si[tid + s];
            if (ov > sv[tid] || (ov == sv[tid] && oi < si[tid])) {
                sv[tid] = ov; si[tid] = oi;
            }
        }
        __syncthreads();
    }
    if (tid == 0) {
        int ns = si[0], ne = si[256];
        if (it == 0) {
            g_start = ns; g_end = ne; g_done = 0;
        } else {
            int nd = (ns == g_start && ne == g_end);
            g_start = ns; g_end = ne;
            g_done = nd;
        }
    }
}

// ---------------------------------------------------------------------------
extern "C" void kernel_launch(void* const* d_in, const int* in_sizes, int n_in,
                              void* d_out, int out_size)
{
    const float* U        = (const float*)d_in[0];
    const float* lstm_Wih = (const float*)d_in[1];
    const float* lstm_Whh = (const float*)d_in[2];
    const float* lstm_bih = (const float*)d_in[3];
    const float* lstm_bhh = (const float*)d_in[4];
    const float* s_fc1w = (const float*)d_in[5];
    const float* s_fc2w = (const float*)d_in[6];
    const float* s_fc2b = (const float*)d_in[7];
    const float* s_fc3w = (const float*)d_in[8];
    const float* s_fc3b = (const float*)d_in[9];
    const float* s_fc4w = (const float*)d_in[10];
    const float* s_fc4b = (const float*)d_in[11];
    const float* e_fc1w = (const float*)d_in[12];
    const float* e_fc2w = (const float*)d_in[13];
    const float* e_fc2b = (const float*)d_in[14];
    const float* e_fc3w = (const float*)d_in[15];
    const float* e_fc3b = (const float*)d_in[16];
    const float* e_fc4w = (const float*)d_in[17];
    const float* e_fc4b = (const float*)d_in[18];
    float* out = (float*)d_out;   // [alphas 4*T | betas 4*T]

    cudaFuncSetAttribute(k_mma, cudaFuncAttributeMaxDynamicSharedMemorySize, SMEM_BYTES);

    dim3 ggrid(NP / BN, TN / BM, 2);   // 25 x 128 x 2 heads

    k_init<<<1, 256>>>();
    k_convU3<<<(TN * K3U + 255) / 256, 256>>>(U);
    k_convB23<<<(NP * K3U + 255) / 256, 256>>>(s_fc2w, 0);
    k_convB23<<<(NP * K3U + 255) / 256, 256>>>(e_fc2w, 1);
    k_zero13<<<(TN * 112 + 255) / 256, 256>>>();
    k_mma<<<ggrid, 256, SMEM_BYTES>>>(0);
    k_convB33<<<(NP * K3M + 255) / 256, 256>>>(s_fc3w, s_fc3b, 0);
    k_convB33<<<(NP * K3M + 255) / 256, 256>>>(e_fc3w, e_fc3b, 1);

    dim3 pgrid((TN * HH + 255) / 256, 2);
    dim3 fgrid((TN * 32) / 256, 2);

    for (int it = 0; it < 4; it++) {
        k_gates<<<100, 256>>>(U, lstm_Wih, lstm_Whh, lstm_bih, lstm_bhh);
        k_lstm_update<<<1, 256>>>();
        k_r<<<50, 256>>>(U, s_fc1w, e_fc1w);
        k_q<<<800, 256>>>(s_fc2w, s_fc2b, e_fc2w, e_fc2b);
        k_pool1<<<pgrid, 256>>>();
        k_mma<<<ggrid, 256, SMEM_BYTES>>>(1);
        k_fc4<<<fgrid, 256>>>(s_fc4w, s_fc4b, e_fc4w, e_fc4b, out, it);
        k_update<<<1, 512>>>(out + (size_t)it * TN, out + (size_t)(4 + it) * TN, it);
    }
}